// round 8
// baseline (speedup 1.0000x reference)
#include <cuda_runtime.h>
#include <math.h>

#define BSZ   64
#define NN    512
#define HID   128
#define NITER 3
#define ROWS  (BSZ*NN)          // 32768

// ---------------- scratch (device globals; no allocations allowed) ----------
__device__ __align__(16) float gH  [ROWS*HID];     // hidden state h
__device__ __align__(16) float gGh [ROWS*384];     // [m | h@Uz+bz | h@Ur+br]
__device__ __align__(16) float gAgg[ROWS*HID];     // A @ m
__device__ __align__(16) float gZ  [ROWS*HID];     // sigmoid(z_pre)
__device__ __align__(16) float gRH [ROWS*HID];     // r * h
__device__ __align__(16) float gP  [ROWS*HID];     // agg@Wh + bh
__device__ __align__(16) float gS  [ROWS*3];       // spatial variable
__device__ __align__(16) float gWh [NITER*HID*384];// [Wm | Uz | Ur] per iter
__device__ __align__(16) float gWa [NITER*HID*384];// [Wz | Wr | Wh] per iter
__device__ __align__(16) float gBh [NITER*384];    // [bm | bz | br]
__device__ __align__(16) float gBa [NITER*384];    // [0 | 0 | bh]

__device__ __forceinline__ float sigm(float x) { return 1.0f / (1.0f + __expf(-x)); }

// ---------------- weight panel prep ----------------------------------------
__global__ void prep_kernel(const float* __restrict__ Wm, const float* __restrict__ bm,
                            const float* __restrict__ Wz, const float* __restrict__ Uz, const float* __restrict__ bz,
                            const float* __restrict__ Wr, const float* __restrict__ Ur, const float* __restrict__ br,
                            const float* __restrict__ Wh, const float* __restrict__ bh)
{
    int idx = blockIdx.x * blockDim.x + threadIdx.x;
    const int total = NITER * HID * 384;
    if (idx < total) {
        int it  = idx / (HID * 384);
        int rem = idx % (HID * 384);
        int k = rem / 384;
        int n = rem % 384;
        int blk = n >> 7;          // 0,1,2
        int c   = n & 127;
        int off = it * HID * HID + k * HID + c;
        gWh[idx] = (blk == 0) ? Wm[off] : (blk == 1 ? Uz[off] : Ur[off]);
        gWa[idx] = (blk == 0) ? Wz[off] : (blk == 1 ? Wr[off] : Wh[off]);
    }
    if (idx < NITER * 384) {
        int it = idx / 384;
        int n  = idx % 384;
        int blk = n >> 7, c = n & 127;
        int off = it * HID + c;
        gBh[idx] = (blk == 0) ? bm[off] : (blk == 1 ? bz[off] : br[off]);
        gBa[idx] = (blk == 2) ? bh[off] : 0.0f;
    }
}

// ---------------- embedding: h = relu(x@W_emb + b) + pos_table --------------
__global__ void embed_kernel(const float* __restrict__ x, const float* __restrict__ W,
                             const float* __restrict__ b, const float* __restrict__ pos)
{
    __shared__ float xs[64];
    int row = blockIdx.x;           // 0..32767 (b*512 + n)
    int c = threadIdx.x;            // 0..127
    if (c < 64) xs[c] = x[(size_t)row * 64 + c];
    __syncthreads();
    float acc = b[c];
#pragma unroll 16
    for (int f = 0; f < 64; f++) acc = fmaf(xs[f], W[f * HID + c], acc);
    int n = row & (NN - 1);
    gH[(size_t)row * HID + c] = fmaxf(acc, 0.0f) + pos[n * HID + c];
}

// ---------------- initial spatial variable ----------------------------------
__global__ void init_s_kernel()
{
    int idx = blockIdx.x * blockDim.x + threadIdx.x;
    if (idx < ROWS) {
        int j = idx & (NN - 1);
        gS[idx * 3 + 0] = (j - 255.5f) * (1.0f / NN);
        gS[idx * 3 + 1] = 0.0f;
        gS[idx * 3 + 2] = 0.0f;
    }
}

// ---------------- adjacency: A = exp(-||si-sj||^2 / 0.01) * mask ------------
__global__ void adj_kernel(const float* __restrict__ mask, float* __restrict__ A)
{
    int b  = blockIdx.y;
    int i0 = blockIdx.x * 8;
    __shared__ float sx[NN], sy[NN], sz[NN];
    const float* s = gS + (size_t)b * NN * 3;
    for (int j = threadIdx.x; j < NN; j += 256) {
        sx[j] = s[j * 3 + 0];
        sy[j] = s[j * 3 + 1];
        sz[j] = s[j * 3 + 2];
    }
    __syncthreads();
#pragma unroll
    for (int r = 0; r < 8; r++) {
        int i = i0 + r;
        float xi = sx[i], yi = sy[i], zi = sz[i];
        size_t base = ((size_t)(b * NN + i)) * NN;
        for (int j = threadIdx.x; j < NN; j += 256) {
            float dx = xi - sx[j], dy = yi - sy[j], dz = zi - sz[j];
            float d2 = dx * dx + dy * dy + dz * dz;
            A[base + j] = __expf(-100.0f * d2) * mask[base + j];
        }
    }
}

// ---------------- positional GRU (warp per node, s updated in place) --------
__global__ void posgru_kernel(const float* __restrict__ Wpz, const float* __restrict__ Upz, const float* __restrict__ bpz,
                              const float* __restrict__ Wpr, const float* __restrict__ Upr, const float* __restrict__ bpr,
                              const float* __restrict__ Wph, const float* __restrict__ Uph, const float* __restrict__ bph)
{
    int gtid = blockIdx.x * blockDim.x + threadIdx.x;
    int node = gtid >> 5;
    int lane = threadIdx.x & 31;
    if (node >= ROWS) return;
    const float* hrow = gH + (size_t)node * HID;
    float pz[3] = {0, 0, 0}, pr[3] = {0, 0, 0}, ph[3] = {0, 0, 0};
#pragma unroll
    for (int q = 0; q < 4; q++) {
        int e = lane + q * 32;
        float hv = hrow[e];
#pragma unroll
        for (int c = 0; c < 3; c++) {
            pz[c] = fmaf(hv, Wpz[e * 3 + c], pz[c]);
            pr[c] = fmaf(hv, Wpr[e * 3 + c], pr[c]);
            ph[c] = fmaf(hv, Wph[e * 3 + c], ph[c]);
        }
    }
#pragma unroll
    for (int off = 16; off; off >>= 1) {
#pragma unroll
        for (int c = 0; c < 3; c++) {
            pz[c] += __shfl_xor_sync(0xffffffffu, pz[c], off);
            pr[c] += __shfl_xor_sync(0xffffffffu, pr[c], off);
            ph[c] += __shfl_xor_sync(0xffffffffu, ph[c], off);
        }
    }
    if (lane == 0) {
        float s0 = gS[node * 3 + 0], s1 = gS[node * 3 + 1], s2 = gS[node * 3 + 2];
        float zs[3], rs[3], ss[3];
#pragma unroll
        for (int c = 0; c < 3; c++)
            zs[c] = sigm(pz[c] + s0 * Upz[c] + s1 * Upz[3 + c] + s2 * Upz[6 + c] + bpz[c]);
#pragma unroll
        for (int c = 0; c < 3; c++)
            rs[c] = sigm(pr[c] + s0 * Upr[c] + s1 * Upr[3 + c] + s2 * Upr[6 + c] + bpr[c]);
        float t0 = rs[0] * s0, t1 = rs[1] * s1, t2 = rs[2] * s2;
#pragma unroll
        for (int c = 0; c < 3; c++)
            ss[c] = tanhf(ph[c] + t0 * Uph[c] + t1 * Uph[3 + c] + t2 * Uph[6 + c] + bph[c]);
        gS[node * 3 + 0] = (1.0f - zs[0]) * s0 + zs[0] * ss[0];
        gS[node * 3 + 1] = (1.0f - zs[1]) * s1 + zs[1] * ss[1];
        gS[node * 3 + 2] = (1.0f - zs[2]) * s2 + zs[2] * ss[2];
    }
}

// ---------------- tiled fp32 SGEMM, 128x128 block, 8x8/thread ---------------
// EPI 0: C = acc
// EPI 1: C = acc + bias[col]; relu on cols < 128   (h-GEMM -> gGh)
// EPI 2: gate epilogue (agg-GEMM): writes gZ / gRH / gP
// EPI 3: GRU blend epilogue (rh@Uh): updates gH in place
template <int EPI>
__global__ void __launch_bounds__(256, 2)
sgemm_kernel(const float* __restrict__ A, int lda, size_t sA,
             const float* __restrict__ B, int ldb, size_t sB,
             float* __restrict__ C, int ldc, size_t sC,
             int K, const float* __restrict__ bias)
{
    const int tid = threadIdx.x;
    const int bm = blockIdx.x, bn = blockIdx.y, bz = blockIdx.z;

    __shared__ __align__(16) float As[8][128];
    __shared__ __align__(16) float Bs[8][128];

    const int arow = tid >> 1;            // 0..127
    const int acol = (tid & 1) * 4;       // 0 or 4
    const int brow = tid >> 5;            // 0..7
    const int bcol = (tid & 31) * 4;      // 0..124

    const float* Aptr = A + bz * sA + (size_t)(bm * 128 + arow) * lda + acol;
    const float* Bptr = B + bz * sB + (size_t)brow * ldb + bn * 128 + bcol;

    const int tx = tid & 15;              // n dim
    const int ty = tid >> 4;              // m dim

    float acc[8][8];
#pragma unroll
    for (int i = 0; i < 8; i++)
#pragma unroll
        for (int j = 0; j < 8; j++) acc[i][j] = 0.0f;

    for (int k0 = 0; k0 < K; k0 += 8) {
        float4 av = *(const float4*)Aptr;  Aptr += 8;
        float4 bv = *(const float4*)Bptr;  Bptr += (size_t)8 * ldb;
        As[acol + 0][arow] = av.x;
        As[acol + 1][arow] = av.y;
        As[acol + 2][arow] = av.z;
        As[acol + 3][arow] = av.w;
        *(float4*)&Bs[brow][bcol] = bv;
        __syncthreads();
#pragma unroll
        for (int kk = 0; kk < 8; kk++) {
            float af[8], bf[8];
            *(float4*)&af[0] = *(const float4*)&As[kk][ty * 8];
            *(float4*)&af[4] = *(const float4*)&As[kk][ty * 8 + 4];
            *(float4*)&bf[0] = *(const float4*)&Bs[kk][tx * 8];
            *(float4*)&bf[4] = *(const float4*)&Bs[kk][tx * 8 + 4];
#pragma unroll
            for (int i = 0; i < 8; i++)
#pragma unroll
                for (int j = 0; j < 8; j++)
                    acc[i][j] = fmaf(af[i], bf[j], acc[i][j]);
        }
        __syncthreads();
    }

    float* Cg = C + bz * sC + (size_t)(bm * 128) * ldc + bn * 128;

#pragma unroll
    for (int i = 0; i < 8; i++) {
        int r = ty * 8 + i;
        int grow = bm * 128 + r;       // global row (valid for non-batched EPIs)
#pragma unroll
        for (int j = 0; j < 8; j++) {
            int c = tx * 8 + j;
            int gcol = bn * 128 + c;
            float v = acc[i][j];
            if (EPI == 0) {
                Cg[(size_t)r * ldc + c] = v;
            } else if (EPI == 1) {
                v += bias[gcol];
                if (gcol < 128) v = fmaxf(v, 0.0f);
                Cg[(size_t)r * ldc + c] = v;
            } else if (EPI == 2) {
                v += bias[gcol];
                int hidx = grow * HID + (gcol & 127);
                if (gcol < 128) {
                    gZ[hidx] = sigm(v + gGh[(size_t)grow * 384 + 128 + gcol]);
                } else if (gcol < 256) {
                    float rr = sigm(v + gGh[(size_t)grow * 384 + 128 + gcol]);
                    gRH[hidx] = rr * gH[hidx];
                } else {
                    gP[hidx] = v;
                }
            } else { // EPI == 3
                int hidx = grow * HID + gcol;
                float z = gZ[hidx];
                float hh = tanhf(v + gP[hidx]);
                float hold = gH[hidx];
                gH[hidx] = (1.0f - z) * hold + z * hh;
            }
        }
    }
}

// ---------------- launch ----------------------------------------------------
extern "C" void kernel_launch(void* const* d_in, const int* in_sizes, int n_in,
                              void* d_out, int out_size)
{
    const float* x     = (const float*)d_in[0];
    const float* mask  = (const float*)d_in[1];
    const float* W_emb = (const float*)d_in[2];
    const float* b_emb = (const float*)d_in[3];
    const float* pos   = (const float*)d_in[4];
    const float* Wm    = (const float*)d_in[5];
    const float* bm    = (const float*)d_in[6];
    const float* Wz    = (const float*)d_in[7];
    const float* Uz    = (const float*)d_in[8];
    const float* bz    = (const float*)d_in[9];
    const float* Wr    = (const float*)d_in[10];
    const float* Ur    = (const float*)d_in[11];
    const float* br    = (const float*)d_in[12];
    const float* Wh    = (const float*)d_in[13];
    const float* Uh    = (const float*)d_in[14];
    const float* bh    = (const float*)d_in[15];
    const float* Wpz   = (const float*)d_in[16];
    const float* Upz   = (const float*)d_in[17];
    const float* bpz   = (const float*)d_in[18];
    const float* Wpr   = (const float*)d_in[19];
    const float* Upr   = (const float*)d_in[20];
    const float* bpr   = (const float*)d_in[21];
    const float* Wph   = (const float*)d_in[22];
    const float* Uph   = (const float*)d_in[23];
    const float* bph   = (const float*)d_in[24];
    float* A = (float*)d_out;

    float *pH, *pGh, *pAgg, *pRH, *pWh, *pWa, *pBh, *pBa;
    cudaGetSymbolAddress((void**)&pH,   gH);
    cudaGetSymbolAddress((void**)&pGh,  gGh);
    cudaGetSymbolAddress((void**)&pAgg, gAgg);
    cudaGetSymbolAddress((void**)&pRH,  gRH);
    cudaGetSymbolAddress((void**)&pWh,  gWh);
    cudaGetSymbolAddress((void**)&pWa,  gWa);
    cudaGetSymbolAddress((void**)&pBh,  gBh);
    cudaGetSymbolAddress((void**)&pBa,  gBa);

    prep_kernel<<<(NITER * HID * 384 + 255) / 256, 256>>>(Wm, bm, Wz, Uz, bz, Wr, Ur, br, Wh, bh);
    embed_kernel<<<ROWS, 128>>>(x, W_emb, b_emb, pos);
    init_s_kernel<<<(ROWS + 255) / 256, 256>>>();
    adj_kernel<<<dim3(NN / 8, BSZ), 256>>>(mask, A);

    for (int it = 0; it < NITER; it++) {
        // Gh = [relu(h@Wm+bm) | h@Uz+bz | h@Ur+br]
        sgemm_kernel<1><<<dim3(ROWS / 128, 3, 1), 256>>>(
            pH, HID, 0,
            pWh + (size_t)it * HID * 384, 384, 0,
            pGh, 384, 0,
            HID, pBh + it * 384);

        // agg[b] = A[b] @ m[b]   (m = Gh cols 0..127, ld 384), batched over 64
        sgemm_kernel<0><<<dim3(NN / 128, 1, BSZ), 256>>>(
            A, NN, (size_t)NN * NN,
            pGh, 384, (size_t)NN * 384,
            pAgg, HID, (size_t)NN * HID,
            NN, pBh);

        // gates: [agg@Wz | agg@Wr | agg@Wh+bh] + fused sigmoid / r*h epilogue
        sgemm_kernel<2><<<dim3(ROWS / 128, 3, 1), 256>>>(
            pAgg, HID, 0,
            pWa + (size_t)it * HID * 384, 384, 0,
            pGh /*unused*/, 384, 0,
            HID, pBa + it * 384);

        // hh = tanh(rh@Uh + p); h = (1-z)h + z*hh  (in place)
        sgemm_kernel<3><<<dim3(ROWS / 128, 1, 1), 256>>>(
            pRH, HID, 0,
            Uh + (size_t)it * HID * HID, HID, 0,
            pH /*unused*/, HID, 0,
            HID, pBa);

        // positional GRU: s <- GRU(h, s) in place
        posgru_kernel<<<ROWS / 8, 256>>>(Wpz, Upz, bpz, Wpr, Upr, bpr, Wph, Uph, bph);

        // A = exp(-||si - sj||^2 / 0.01) * mask  (final iteration leaves answer in d_out)
        adj_kernel<<<dim3(NN / 8, BSZ), 256>>>(mask, A);
    }
}

// round 9
// speedup vs baseline: 1.0008x; 1.0008x over previous
#include <cuda_runtime.h>
#include <math.h>

#define BSZ   64
#define NN    512
#define HID   128
#define NITER 3
#define ROWS  (BSZ*NN)          // 32768

// ---------------- scratch (device globals; no allocations allowed) ----------
__device__ __align__(16) float gH  [ROWS*HID];     // hidden state h
__device__ __align__(16) float gGh [ROWS*384];     // [m | h@Uz+bz | h@Ur+br]
__device__ __align__(16) float gAgg[ROWS*HID];     // A @ m
__device__ __align__(16) float gZ  [ROWS*HID];     // sigmoid(z_pre)
__device__ __align__(16) float gRH [ROWS*HID];     // r * h
__device__ __align__(16) float gP  [ROWS*HID];     // agg@Wh + bh
__device__ __align__(16) float gS  [ROWS*3];       // spatial variable
__device__ __align__(16) float gWh [NITER*HID*384];// [Wm | Uz | Ur] per iter
__device__ __align__(16) float gWa [NITER*HID*384];// [Wz | Wr | Wh] per iter
__device__ __align__(16) float gBh [NITER*384];    // [bm | bz | br]
__device__ __align__(16) float gBa [NITER*384];    // [0 | 0 | bh]

__device__ __forceinline__ float sigm(float x) { return 1.0f / (1.0f + __expf(-x)); }

// ---------------- weight panel prep ----------------------------------------
__global__ void prep_kernel(const float* __restrict__ Wm, const float* __restrict__ bm,
                            const float* __restrict__ Wz, const float* __restrict__ Uz, const float* __restrict__ bz,
                            const float* __restrict__ Wr, const float* __restrict__ Ur, const float* __restrict__ br,
                            const float* __restrict__ Wh, const float* __restrict__ bh)
{
    int idx = blockIdx.x * blockDim.x + threadIdx.x;
    const int total = NITER * HID * 384;
    if (idx < total) {
        int it  = idx / (HID * 384);
        int rem = idx % (HID * 384);
        int k = rem / 384;
        int n = rem % 384;
        int blk = n >> 7;          // 0,1,2
        int c   = n & 127;
        int off = it * HID * HID + k * HID + c;
        gWh[idx] = (blk == 0) ? Wm[off] : (blk == 1 ? Uz[off] : Ur[off]);
        gWa[idx] = (blk == 0) ? Wz[off] : (blk == 1 ? Wr[off] : Wh[off]);
    }
    if (idx < NITER * 384) {
        int it = idx / 384;
        int n  = idx % 384;
        int blk = n >> 7, c = n & 127;
        int off = it * HID + c;
        gBh[idx] = (blk == 0) ? bm[off] : (blk == 1 ? bz[off] : br[off]);
        gBa[idx] = (blk == 2) ? bh[off] : 0.0f;
    }
}

// ---------------- embedding: h = relu(x@W_emb + b) + pos_table --------------
__global__ void embed_kernel(const float* __restrict__ x, const float* __restrict__ W,
                             const float* __restrict__ b, const float* __restrict__ pos)
{
    __shared__ float xs[64];
    int row = blockIdx.x;           // 0..32767 (b*512 + n)
    int c = threadIdx.x;            // 0..127
    if (c < 64) xs[c] = x[(size_t)row * 64 + c];
    __syncthreads();
    float acc = b[c];
#pragma unroll 16
    for (int f = 0; f < 64; f++) acc = fmaf(xs[f], W[f * HID + c], acc);
    int n = row & (NN - 1);
    gH[(size_t)row * HID + c] = fmaxf(acc, 0.0f) + pos[n * HID + c];
}

// ---------------- initial spatial variable ----------------------------------
__global__ void init_s_kernel()
{
    int idx = blockIdx.x * blockDim.x + threadIdx.x;
    if (idx < ROWS) {
        int j = idx & (NN - 1);
        gS[idx * 3 + 0] = (j - 255.5f) * (1.0f / NN);
        gS[idx * 3 + 1] = 0.0f;
        gS[idx * 3 + 2] = 0.0f;
    }
}

// ---------------- adjacency: A = exp(-||si-sj||^2 / 0.01) * mask ------------
__global__ void adj_kernel(const float* __restrict__ mask, float* __restrict__ A)
{
    int b  = blockIdx.y;
    int i0 = blockIdx.x * 8;
    __shared__ float sx[NN], sy[NN], sz[NN];
    const float* s = gS + (size_t)b * NN * 3;
    for (int j = threadIdx.x; j < NN; j += 256) {
        sx[j] = s[j * 3 + 0];
        sy[j] = s[j * 3 + 1];
        sz[j] = s[j * 3 + 2];
    }
    __syncthreads();
#pragma unroll
    for (int r = 0; r < 8; r++) {
        int i = i0 + r;
        float xi = sx[i], yi = sy[i], zi = sz[i];
        size_t base = ((size_t)(b * NN + i)) * NN;
        for (int j = threadIdx.x; j < NN; j += 256) {
            float dx = xi - sx[j], dy = yi - sy[j], dz = zi - sz[j];
            float d2 = dx * dx + dy * dy + dz * dz;
            A[base + j] = __expf(-100.0f * d2) * mask[base + j];
        }
    }
}

// ---------------- positional GRU (warp per node, s updated in place) --------
__global__ void posgru_kernel(const float* __restrict__ Wpz, const float* __restrict__ Upz, const float* __restrict__ bpz,
                              const float* __restrict__ Wpr, const float* __restrict__ Upr, const float* __restrict__ bpr,
                              const float* __restrict__ Wph, const float* __restrict__ Uph, const float* __restrict__ bph)
{
    int gtid = blockIdx.x * blockDim.x + threadIdx.x;
    int node = gtid >> 5;
    int lane = threadIdx.x & 31;
    if (node >= ROWS) return;
    const float* hrow = gH + (size_t)node * HID;
    float pz[3] = {0, 0, 0}, pr[3] = {0, 0, 0}, ph[3] = {0, 0, 0};
#pragma unroll
    for (int q = 0; q < 4; q++) {
        int e = lane + q * 32;
        float hv = hrow[e];
#pragma unroll
        for (int c = 0; c < 3; c++) {
            pz[c] = fmaf(hv, Wpz[e * 3 + c], pz[c]);
            pr[c] = fmaf(hv, Wpr[e * 3 + c], pr[c]);
            ph[c] = fmaf(hv, Wph[e * 3 + c], ph[c]);
        }
    }
#pragma unroll
    for (int off = 16; off; off >>= 1) {
#pragma unroll
        for (int c = 0; c < 3; c++) {
            pz[c] += __shfl_xor_sync(0xffffffffu, pz[c], off);
            pr[c] += __shfl_xor_sync(0xffffffffu, pr[c], off);
            ph[c] += __shfl_xor_sync(0xffffffffu, ph[c], off);
        }
    }
    if (lane == 0) {
        float s0 = gS[node * 3 + 0], s1 = gS[node * 3 + 1], s2 = gS[node * 3 + 2];
        float zs[3], rs[3], ss[3];
#pragma unroll
        for (int c = 0; c < 3; c++)
            zs[c] = sigm(pz[c] + s0 * Upz[c] + s1 * Upz[3 + c] + s2 * Upz[6 + c] + bpz[c]);
#pragma unroll
        for (int c = 0; c < 3; c++)
            rs[c] = sigm(pr[c] + s0 * Upr[c] + s1 * Upr[3 + c] + s2 * Upr[6 + c] + bpr[c]);
        float t0 = rs[0] * s0, t1 = rs[1] * s1, t2 = rs[2] * s2;
#pragma unroll
        for (int c = 0; c < 3; c++)
            ss[c] = tanhf(ph[c] + t0 * Uph[c] + t1 * Uph[3 + c] + t2 * Uph[6 + c] + bph[c]);
        gS[node * 3 + 0] = (1.0f - zs[0]) * s0 + zs[0] * ss[0];
        gS[node * 3 + 1] = (1.0f - zs[1]) * s1 + zs[1] * ss[1];
        gS[node * 3 + 2] = (1.0f - zs[2]) * s2 + zs[2] * ss[2];
    }
}

// ---------------- tiled fp32 SGEMM, 128x128 block, 8x8/thread ---------------
// EPI 0: C = acc
// EPI 1: C = acc + bias[col]; relu on cols < 128   (h-GEMM -> gGh)
// EPI 2: gate epilogue (agg-GEMM): writes gZ / gRH / gP
// EPI 3: GRU blend epilogue (rh@Uh): updates gH in place
template <int EPI>
__global__ void __launch_bounds__(256, 2)
sgemm_kernel(const float* __restrict__ A, int lda, size_t sA,
             const float* __restrict__ B, int ldb, size_t sB,
             float* __restrict__ C, int ldc, size_t sC,
             int K, const float* __restrict__ bias)
{
    const int tid = threadIdx.x;
    const int bm = blockIdx.x, bn = blockIdx.y, bz = blockIdx.z;

    __shared__ __align__(16) float As[8][128];
    __shared__ __align__(16) float Bs[8][128];

    const int arow = tid >> 1;            // 0..127
    const int acol = (tid & 1) * 4;       // 0 or 4
    const int brow = tid >> 5;            // 0..7
    const int bcol = (tid & 31) * 4;      // 0..124

    const float* Aptr = A + bz * sA + (size_t)(bm * 128 + arow) * lda + acol;
    const float* Bptr = B + bz * sB + (size_t)brow * ldb + bn * 128 + bcol;

    const int tx = tid & 15;              // n dim
    const int ty = tid >> 4;              // m dim

    float acc[8][8];
#pragma unroll
    for (int i = 0; i < 8; i++)
#pragma unroll
        for (int j = 0; j < 8; j++) acc[i][j] = 0.0f;

    for (int k0 = 0; k0 < K; k0 += 8) {
        float4 av = *(const float4*)Aptr;  Aptr += 8;
        float4 bv = *(const float4*)Bptr;  Bptr += (size_t)8 * ldb;
        As[acol + 0][arow] = av.x;
        As[acol + 1][arow] = av.y;
        As[acol + 2][arow] = av.z;
        As[acol + 3][arow] = av.w;
        *(float4*)&Bs[brow][bcol] = bv;
        __syncthreads();
#pragma unroll
        for (int kk = 0; kk < 8; kk++) {
            float af[8], bf[8];
            *(float4*)&af[0] = *(const float4*)&As[kk][ty * 8];
            *(float4*)&af[4] = *(const float4*)&As[kk][ty * 8 + 4];
            *(float4*)&bf[0] = *(const float4*)&Bs[kk][tx * 8];
            *(float4*)&bf[4] = *(const float4*)&Bs[kk][tx * 8 + 4];
#pragma unroll
            for (int i = 0; i < 8; i++)
#pragma unroll
                for (int j = 0; j < 8; j++)
                    acc[i][j] = fmaf(af[i], bf[j], acc[i][j]);
        }
        __syncthreads();
    }

    float* Cg = C + bz * sC + (size_t)(bm * 128) * ldc + bn * 128;

#pragma unroll
    for (int i = 0; i < 8; i++) {
        int r = ty * 8 + i;
        int grow = bm * 128 + r;       // global row (valid for non-batched EPIs)
#pragma unroll
        for (int j = 0; j < 8; j++) {
            int c = tx * 8 + j;
            int gcol = bn * 128 + c;
            float v = acc[i][j];
            if (EPI == 0) {
                Cg[(size_t)r * ldc + c] = v;
            } else if (EPI == 1) {
                v += bias[gcol];
                if (gcol < 128) v = fmaxf(v, 0.0f);
                Cg[(size_t)r * ldc + c] = v;
            } else if (EPI == 2) {
                v += bias[gcol];
                int hidx = grow * HID + (gcol & 127);
                if (gcol < 128) {
                    gZ[hidx] = sigm(v + gGh[(size_t)grow * 384 + 128 + gcol]);
                } else if (gcol < 256) {
                    float rr = sigm(v + gGh[(size_t)grow * 384 + 128 + gcol]);
                    gRH[hidx] = rr * gH[hidx];
                } else {
                    gP[hidx] = v;
                }
            } else { // EPI == 3
                int hidx = grow * HID + gcol;
                float z = gZ[hidx];
                float hh = tanhf(v + gP[hidx]);
                float hold = gH[hidx];
                gH[hidx] = (1.0f - z) * hold + z * hh;
            }
        }
    }
}

// ---------------- launch ----------------------------------------------------
extern "C" void kernel_launch(void* const* d_in, const int* in_sizes, int n_in,
                              void* d_out, int out_size)
{
    const float* x     = (const float*)d_in[0];
    const float* mask  = (const float*)d_in[1];
    const float* W_emb = (const float*)d_in[2];
    const float* b_emb = (const float*)d_in[3];
    const float* pos   = (const float*)d_in[4];
    const float* Wm    = (const float*)d_in[5];
    const float* bm    = (const float*)d_in[6];
    const float* Wz    = (const float*)d_in[7];
    const float* Uz    = (const float*)d_in[8];
    const float* bz    = (const float*)d_in[9];
    const float* Wr    = (const float*)d_in[10];
    const float* Ur    = (const float*)d_in[11];
    const float* br    = (const float*)d_in[12];
    const float* Wh    = (const float*)d_in[13];
    const float* Uh    = (const float*)d_in[14];
    const float* bh    = (const float*)d_in[15];
    const float* Wpz   = (const float*)d_in[16];
    const float* Upz   = (const float*)d_in[17];
    const float* bpz   = (const float*)d_in[18];
    const float* Wpr   = (const float*)d_in[19];
    const float* Upr   = (const float*)d_in[20];
    const float* bpr   = (const float*)d_in[21];
    const float* Wph   = (const float*)d_in[22];
    const float* Uph   = (const float*)d_in[23];
    const float* bph   = (const float*)d_in[24];
    float* A = (float*)d_out;

    float *pH, *pGh, *pAgg, *pRH, *pWh, *pWa, *pBh, *pBa;
    cudaGetSymbolAddress((void**)&pH,   gH);
    cudaGetSymbolAddress((void**)&pGh,  gGh);
    cudaGetSymbolAddress((void**)&pAgg, gAgg);
    cudaGetSymbolAddress((void**)&pRH,  gRH);
    cudaGetSymbolAddress((void**)&pWh,  gWh);
    cudaGetSymbolAddress((void**)&pWa,  gWa);
    cudaGetSymbolAddress((void**)&pBh,  gBh);
    cudaGetSymbolAddress((void**)&pBa,  gBa);

    prep_kernel<<<(NITER * HID * 384 + 255) / 256, 256>>>(Wm, bm, Wz, Uz, bz, Wr, Ur, br, Wh, bh);
    embed_kernel<<<ROWS, 128>>>(x, W_emb, b_emb, pos);
    init_s_kernel<<<(ROWS + 255) / 256, 256>>>();
    adj_kernel<<<dim3(NN / 8, BSZ), 256>>>(mask, A);

    for (int it = 0; it < NITER; it++) {
        // Gh = [relu(h@Wm+bm) | h@Uz+bz | h@Ur+br]
        sgemm_kernel<1><<<dim3(ROWS / 128, 3, 1), 256>>>(
            pH, HID, 0,
            pWh + (size_t)it * HID * 384, 384, 0,
            pGh, 384, 0,
            HID, pBh + it * 384);

        // agg[b] = A[b] @ m[b]   (m = Gh cols 0..127, ld 384), batched over 64
        sgemm_kernel<0><<<dim3(NN / 128, 1, BSZ), 256>>>(
            A, NN, (size_t)NN * NN,
            pGh, 384, (size_t)NN * 384,
            pAgg, HID, (size_t)NN * HID,
            NN, pBh);

        // gates: [agg@Wz | agg@Wr | agg@Wh+bh] + fused sigmoid / r*h epilogue
        sgemm_kernel<2><<<dim3(ROWS / 128, 3, 1), 256>>>(
            pAgg, HID, 0,
            pWa + (size_t)it * HID * 384, 384, 0,
            pGh /*unused*/, 384, 0,
            HID, pBa + it * 384);

        // hh = tanh(rh@Uh + p); h = (1-z)h + z*hh  (in place)
        sgemm_kernel<3><<<dim3(ROWS / 128, 1, 1), 256>>>(
            pRH, HID, 0,
            Uh + (size_t)it * HID * HID, HID, 0,
            pH /*unused*/, HID, 0,
            HID, pBa);

        // positional GRU: s <- GRU(h, s) in place
        posgru_kernel<<<ROWS / 8, 256>>>(Wpz, Upz, bpz, Wpr, Upr, bpr, Wph, Uph, bph);

        // A = exp(-||si - sj||^2 / 0.01) * mask  (final iteration leaves answer in d_out)
        adj_kernel<<<dim3(NN / 8, BSZ), 256>>>(mask, A);
    }
}

// round 13
// speedup vs baseline: 2.0172x; 2.0156x over previous
#include <cuda_runtime.h>
#include <cuda_bf16.h>
#include <stdint.h>
#include <math.h>

#define BSZ   64
#define NN    512
#define HID   128
#define NITER 3
#define ROWS  (BSZ*NN)

// ---------------- scratch ----------------------------------------------------
__device__ __align__(16) float gH   [ROWS*HID];
__device__ __align__(16) float gZ   [ROWS*HID];
__device__ __align__(16) float gP   [ROWS*HID];
__device__ __align__(16) float gZpre[ROWS*HID];
__device__ __align__(16) float gRpre[ROWS*HID];
__device__ __align__(16) float gS   [ROWS*3];
__device__ __align__(16) __nv_bfloat16 hHi [ROWS*HID], hLo [ROWS*HID];
__device__ __align__(16) __nv_bfloat16 AHi [(size_t)BSZ*NN*NN], ALo [(size_t)BSZ*NN*NN];
__device__ __align__(16) __nv_bfloat16 mHi [ROWS*HID], mLo [ROWS*HID];
__device__ __align__(16) __nv_bfloat16 aggHi[ROWS*HID], aggLo[ROWS*HID];
__device__ __align__(16) __nv_bfloat16 rhHi [ROWS*HID], rhLo [ROWS*HID];
__device__ __align__(16) __nv_bfloat16 B1Hi[NITER*HID*384], B1Lo[NITER*HID*384]; // [k][n]
__device__ __align__(16) __nv_bfloat16 B3Hi[NITER*HID*384], B3Lo[NITER*HID*384]; // [k][n]
__device__ __align__(16) __nv_bfloat16 B4Hi[NITER*HID*HID], B4Lo[NITER*HID*HID]; // [k][n]
__device__ __align__(16) float gB1[NITER*384];
__device__ __align__(16) float gB3[NITER*384];

__device__ __forceinline__ float sigm(float x) { return 1.0f / (1.0f + __expf(-x)); }

__device__ __forceinline__ void split2(float v, __nv_bfloat16& hi, __nv_bfloat16& lo)
{
    __nv_bfloat16 h = __float2bfloat16(v);
    hi = h;
    lo = __float2bfloat16(v - __bfloat162float(h));
}

__device__ __forceinline__ uint32_t smem_u32(const void* p)
{
    uint32_t a;
    asm("{ .reg .u64 t; cvta.to.shared.u64 t, %1; cvt.u32.u64 %0, t; }" : "=r"(a) : "l"(p));
    return a;
}

// ---------------- mma.sync building blocks -----------------------------------
__device__ __forceinline__ void mma16816(float* d, const uint32_t* a, const uint32_t* b)
{
    asm volatile(
        "mma.sync.aligned.m16n8k16.row.col.f32.bf16.bf16.f32 "
        "{%0,%1,%2,%3}, {%4,%5,%6,%7}, {%8,%9}, {%0,%1,%2,%3};"
        : "+f"(d[0]), "+f"(d[1]), "+f"(d[2]), "+f"(d[3])
        : "r"(a[0]), "r"(a[1]), "r"(a[2]), "r"(a[3]), "r"(b[0]), "r"(b[1]));
}

__device__ __forceinline__ void ldsm4(uint32_t* r, uint32_t addr)
{
    asm volatile("ldmatrix.sync.aligned.m8n8.x4.shared.b16 {%0,%1,%2,%3}, [%4];"
                 : "=r"(r[0]), "=r"(r[1]), "=r"(r[2]), "=r"(r[3]) : "r"(addr));
}

__device__ __forceinline__ void ldsm4t(uint32_t* r, uint32_t addr)
{
    asm volatile("ldmatrix.sync.aligned.m8n8.x4.trans.shared.b16 {%0,%1,%2,%3}, [%4];"
                 : "=r"(r[0]), "=r"(r[1]), "=r"(r[2]), "=r"(r[3]) : "r"(addr));
}

__device__ __forceinline__ void cp16(uint32_t s, const void* g)
{
    asm volatile("cp.async.cg.shared.global [%0], [%1], 16;" :: "r"(s), "l"(g));
}

#define ASTRIDE 40                      // bf16 elems per A smem row (32 + 8 pad)
#define BSTRIDE 136                     // bf16 elems per B smem row (128 + 8 pad)
#define A_TILE_B (128*ASTRIDE*2)        // 10240 bytes
#define B_TILE_B (32*BSTRIDE*2)         // 8704 bytes
#define STAGE_B  (2*A_TILE_B + 2*B_TILE_B)   // 37888
#define SMEM_B   (2*STAGE_B)                 // 75776

__device__ __forceinline__ void load_stage(
    uint32_t sb, int buf, int tid, int k0,
    const __nv_bfloat16* Abh, const __nv_bfloat16* Abl, int lda,
    const __nv_bfloat16* Bbh, const __nv_bfloat16* Bbl, int ldb)
{
    uint32_t st = sb + buf * STAGE_B;
    // A tiles: 128 rows x 32 k, hi+lo -> 1024 x 16B chunks
#pragma unroll
    for (int i = 0; i < 4; i++) {
        int id = tid + i * 256;
        int t  = id >> 9;                 // 0 = hi, 1 = lo (uniform per unrolled i)
        int r  = (id >> 2) & 127;
        int c  = id & 3;
        const __nv_bfloat16* g = (t ? Abl : Abh) + (long long)r * lda + k0 + c * 8;
        cp16(st + t * A_TILE_B + r * (ASTRIDE * 2) + c * 16, g);
    }
    // B tiles: 32 k-rows x 128 n, hi+lo -> 1024 x 16B chunks
#pragma unroll
    for (int i = 0; i < 4; i++) {
        int id = tid + i * 256;
        int t  = id >> 9;
        int r  = (id >> 4) & 31;
        int c  = id & 15;
        const __nv_bfloat16* g = (t ? Bbl : Bbh) + (long long)(k0 + r) * ldb + c * 8;
        cp16(st + 2 * A_TILE_B + t * B_TILE_B + r * (BSTRIDE * 2) + c * 16, g);
    }
    asm volatile("cp.async.commit_group;" ::: "memory");
}

// ---------------- split-bf16 tensor-core GEMM (mma.sync) ---------------------
// D[128x128] fp32 = A(hi/lo)[M x K] @ B(hi/lo)[K x N], epilogue from registers.
// EPI 0: agg -> agg splits (batched over bz)
// EPI 1: yy0: m=relu(.+b) -> m splits ; yy1: gZpre ; yy2: gRpre
// EPI 2: yy0: gZ=sigm(.+gZpre) ; yy1: rh=sigm(.+gRpre)*h -> splits ; yy2: gP=.+bh
// EPI 3: h = (1-z) h + z tanh(. + gP) -> gH + h splits
template <int EPI>
__global__ void __launch_bounds__(256)
mma_gemm(const __nv_bfloat16* __restrict__ Ah, const __nv_bfloat16* __restrict__ Al,
         int lda, long long sA,
         const __nv_bfloat16* __restrict__ Bh, const __nv_bfloat16* __restrict__ Bl,
         int ldb, long long sB,
         int K, const float* __restrict__ bias)
{
    extern __shared__ char smem[];
    const uint32_t sb = smem_u32(smem);
    const int tid  = threadIdx.x;
    const int wid  = tid >> 5, lane = tid & 31;
    const int wm   = wid >> 1, wn = wid & 1;          // 4 x 2 warp grid
    const int bm   = blockIdx.x, yy = blockIdx.y, bz = blockIdx.z;

    const __nv_bfloat16* Abh = Ah + bz * sA + (long long)(bm * 128) * lda;
    const __nv_bfloat16* Abl = Al + bz * sA + (long long)(bm * 128) * lda;
    const __nv_bfloat16* Bbh = Bh + bz * sB + yy * 128;
    const __nv_bfloat16* Bbl = Bl + bz * sB + yy * 128;

    float acc[2][8][4];
#pragma unroll
    for (int i = 0; i < 2; i++)
#pragma unroll
        for (int j = 0; j < 8; j++)
#pragma unroll
            for (int e = 0; e < 4; e++) acc[i][j][e] = 0.0f;

    // lane-invariant smem fragment addresses
    const uint32_t aoff = (uint32_t)((wm * 32 + (lane & 15)) * (ASTRIDE * 2) + (lane >> 4) * 16);
    const int q = lane >> 3;
    const uint32_t boff = (uint32_t)(2 * A_TILE_B
                        + ((q & 1) * 8 + (lane & 7)) * (BSTRIDE * 2)
                        + (wn * 64 + (q >> 1) * 8) * 2);

    const int nstage = K >> 5;
    load_stage(sb, 0, tid, 0, Abh, Abl, lda, Bbh, Bbl, ldb);

    for (int kt = 0; kt < nstage; kt++) {
        asm volatile("cp.async.wait_group 0;" ::: "memory");
        __syncthreads();
        if (kt + 1 < nstage)
            load_stage(sb, (kt + 1) & 1, tid, (kt + 1) << 5, Abh, Abl, lda, Bbh, Bbl, ldb);

        const uint32_t st = sb + (kt & 1) * STAGE_B;
#pragma unroll
        for (int j = 0; j < 2; j++) {                 // two k16 per stage
            uint32_t ah[2][4], al[2][4];
#pragma unroll
            for (int mt = 0; mt < 2; mt++) {
                uint32_t a0 = st + aoff + mt * 16 * (ASTRIDE * 2) + j * 32;
                ldsm4(ah[mt], a0);
                ldsm4(al[mt], a0 + A_TILE_B);
            }
#pragma unroll
            for (int np = 0; np < 4; np++) {
                uint32_t bh[4], bl[4];
                uint32_t b0 = st + boff + j * 16 * (BSTRIDE * 2) + np * 32;
                ldsm4t(bh, b0);
                ldsm4t(bl, b0 + B_TILE_B);
#pragma unroll
                for (int mt = 0; mt < 2; mt++) {
                    mma16816(acc[mt][2 * np],     ah[mt], bh);       // hi*hi
                    mma16816(acc[mt][2 * np],     ah[mt], bl);       // hi*lo
                    mma16816(acc[mt][2 * np],     al[mt], bh);       // lo*hi
                    mma16816(acc[mt][2 * np + 1], ah[mt], bh + 2);
                    mma16816(acc[mt][2 * np + 1], ah[mt], bl + 2);
                    mma16816(acc[mt][2 * np + 1], al[mt], bh + 2);
                }
            }
        }
    }

    // ---------------- register epilogue ----------------
    const int lrow = lane >> 2;
    const int lcol = (lane & 3) * 2;
#pragma unroll
    for (int mt = 0; mt < 2; mt++)
#pragma unroll
    for (int nt = 0; nt < 8; nt++)
#pragma unroll
    for (int half = 0; half < 2; half++) {
        const int row = bm * 128 + wm * 32 + mt * 16 + lrow + half * 8;
        const int col = wn * 64 + nt * 8 + lcol;
        float v0 = acc[mt][nt][half * 2 + 0];
        float v1 = acc[mt][nt][half * 2 + 1];

        if (EPI == 0) {
            long long base = ((long long)bz * NN + row) * HID + col;
            __nv_bfloat162 hv, lv;
            split2(v0, hv.x, lv.x); split2(v1, hv.y, lv.y);
            *(__nv_bfloat162*)(aggHi + base) = hv;
            *(__nv_bfloat162*)(aggLo + base) = lv;
        } else if (EPI == 1) {
            int base = row * HID + col;
            if (yy == 0) {
                float m0 = fmaxf(v0 + bias[col],     0.0f);
                float m1 = fmaxf(v1 + bias[col + 1], 0.0f);
                __nv_bfloat162 hv, lv;
                split2(m0, hv.x, lv.x); split2(m1, hv.y, lv.y);
                *(__nv_bfloat162*)(mHi + base) = hv;
                *(__nv_bfloat162*)(mLo + base) = lv;
            } else {
                float* out = (yy == 1) ? gZpre : gRpre;
                float2 o;
                o.x = v0 + bias[yy * 128 + col];
                o.y = v1 + bias[yy * 128 + col + 1];
                *(float2*)(out + base) = o;
            }
        } else if (EPI == 2) {
            int base = row * HID + col;
            if (yy == 0) {
                float2 zp = *(const float2*)(gZpre + base);
                float2 o; o.x = sigm(v0 + zp.x); o.y = sigm(v1 + zp.y);
                *(float2*)(gZ + base) = o;
            } else if (yy == 1) {
                float2 rp = *(const float2*)(gRpre + base);
                float2 hv2 = *(const float2*)(gH + base);
                float rh0 = sigm(v0 + rp.x) * hv2.x;
                float rh1 = sigm(v1 + rp.y) * hv2.y;
                __nv_bfloat162 hv, lv;
                split2(rh0, hv.x, lv.x); split2(rh1, hv.y, lv.y);
                *(__nv_bfloat162*)(rhHi + base) = hv;
                *(__nv_bfloat162*)(rhLo + base) = lv;
            } else {
                float2 o;
                o.x = v0 + bias[256 + col];
                o.y = v1 + bias[256 + col + 1];
                *(float2*)(gP + base) = o;
            }
        } else { // EPI == 3
            int base = row * HID + col;
            float2 z  = *(const float2*)(gZ + base);
            float2 p  = *(const float2*)(gP + base);
            float2 h2 = *(const float2*)(gH + base);
            float hn0 = fmaf(z.x, tanhf(v0 + p.x) - h2.x, h2.x);
            float hn1 = fmaf(z.y, tanhf(v1 + p.y) - h2.y, h2.y);
            float2 o; o.x = hn0; o.y = hn1;
            *(float2*)(gH + base) = o;
            __nv_bfloat162 hv, lv;
            split2(hn0, hv.x, lv.x); split2(hn1, hv.y, lv.y);
            *(__nv_bfloat162*)(hHi + base) = hv;
            *(__nv_bfloat162*)(hLo + base) = lv;
        }
    }
}

// ---------------- weight panel prep ([k][n] natural layout) ------------------
__global__ void prep_kernel(const float* __restrict__ Wm, const float* __restrict__ bm,
                            const float* __restrict__ Wz, const float* __restrict__ Uz, const float* __restrict__ bz,
                            const float* __restrict__ Wr, const float* __restrict__ Ur, const float* __restrict__ br,
                            const float* __restrict__ Wh, const float* __restrict__ Uh, const float* __restrict__ bh)
{
    int idx = blockIdx.x * 256 + threadIdx.x;
    if (idx >= NITER * 384 * 128) return;
    int it  = idx / (384 * 128);
    int rem = idx % (384 * 128);
    int n = rem / 128;            // output channel across 3 panels
    int k = rem % 128;
    int blk = n >> 7, c = n & 127;
    int off = it * HID * HID + k * HID + c;
    float w1 = (blk == 0) ? Wm[off] : (blk == 1 ? Uz[off] : Ur[off]);
    float w3 = (blk == 0) ? Wz[off] : (blk == 1 ? Wr[off] : Wh[off]);
    int po = it * 384 * 128 + k * 384 + n;   // [k][n]
    split2(w1, B1Hi[po], B1Lo[po]);
    split2(w3, B3Hi[po], B3Lo[po]);
    if (blk == 0) {
        int b4 = it * HID * HID + k * 128 + c;   // Uh natural [k][n]
        split2(Uh[off], B4Hi[b4], B4Lo[b4]);
    }
    if (k == 0) {
        gB1[it * 384 + n] = (blk == 0) ? bm[it * HID + c] : (blk == 1 ? bz[it * HID + c] : br[it * HID + c]);
        gB3[it * 384 + n] = (blk == 2) ? bh[it * HID + c] : 0.0f;
    }
}

// ---------------- embedding ---------------------------------------------------
__global__ void embed_kernel(const float* __restrict__ x, const float* __restrict__ W,
                             const float* __restrict__ b, const float* __restrict__ pos)
{
    __shared__ float xs[64];
    int row = blockIdx.x;
    int c = threadIdx.x;
    if (c < 64) xs[c] = x[(size_t)row * 64 + c];
    __syncthreads();
    float acc = b[c];
#pragma unroll 16
    for (int f = 0; f < 64; f++) acc = fmaf(xs[f], W[f * HID + c], acc);
    int n = row & (NN - 1);
    float h = fmaxf(acc, 0.0f) + pos[n * HID + c];
    int o = row * HID + c;
    gH[o] = h;
    split2(h, hHi[o], hLo[o]);
}

__global__ void init_s_kernel()
{
    int idx = blockIdx.x * blockDim.x + threadIdx.x;
    if (idx < ROWS) {
        int j = idx & (NN - 1);
        gS[idx * 3 + 0] = (j - 255.5f) * (1.0f / NN);
        gS[idx * 3 + 1] = 0.0f;
        gS[idx * 3 + 2] = 0.0f;
    }
}

// ---------------- adjacency: MODE 0 -> bf16 splits, MODE 1 -> fp32 d_out ------
template <int MODE>
__global__ void adj_t(const float* __restrict__ mask, float* __restrict__ Aout)
{
    int b  = blockIdx.y;
    int i0 = blockIdx.x * 8;
    __shared__ float sx[NN], sy[NN], sz[NN];
    const float* s = gS + (size_t)b * NN * 3;
    for (int j = threadIdx.x; j < NN; j += 128) {
        sx[j] = s[j * 3 + 0]; sy[j] = s[j * 3 + 1]; sz[j] = s[j * 3 + 2];
    }
    __syncthreads();
    int j0 = threadIdx.x * 4;
#pragma unroll
    for (int rr = 0; rr < 8; rr++) {
        int i = i0 + rr;
        float xi = sx[i], yi = sy[i], zi = sz[i];
        size_t base = ((size_t)b * NN + i) * NN + j0;
        float4 mv = *(const float4*)(mask + base);
        float a[4];
#pragma unroll
        for (int t = 0; t < 4; t++) {
            int j = j0 + t;
            float dx = xi - sx[j], dy = yi - sy[j], dz = zi - sz[j];
            a[t] = __expf(-100.0f * (dx * dx + dy * dy + dz * dz)) * ((&mv.x)[t]);
        }
        if (MODE == 1) {
            float4 ov; ov.x = a[0]; ov.y = a[1]; ov.z = a[2]; ov.w = a[3];
            *(float4*)(Aout + base) = ov;
        } else {
            __nv_bfloat16 h2[4], l2[4];
#pragma unroll
            for (int t = 0; t < 4; t++) split2(a[t], h2[t], l2[t]);
            __nv_bfloat162 p0; p0.x = h2[0]; p0.y = h2[1];
            __nv_bfloat162 p1; p1.x = h2[2]; p1.y = h2[3];
            __nv_bfloat162 q0; q0.x = l2[0]; q0.y = l2[1];
            __nv_bfloat162 q1; q1.x = l2[2]; q1.y = l2[3];
            *(__nv_bfloat162*)(AHi + base)     = p0;
            *(__nv_bfloat162*)(AHi + base + 2) = p1;
            *(__nv_bfloat162*)(ALo + base)     = q0;
            *(__nv_bfloat162*)(ALo + base + 2) = q1;
        }
    }
}

// ---------------- positional GRU ------------------------------------------------
__global__ void posgru_kernel(const float* __restrict__ Wpz, const float* __restrict__ Upz, const float* __restrict__ bpz,
                              const float* __restrict__ Wpr, const float* __restrict__ Upr, const float* __restrict__ bpr,
                              const float* __restrict__ Wph, const float* __restrict__ Uph, const float* __restrict__ bph)
{
    int gtid = blockIdx.x * blockDim.x + threadIdx.x;
    int node = gtid >> 5;
    int lane = threadIdx.x & 31;
    if (node >= ROWS) return;
    const float* hrow = gH + (size_t)node * HID;
    float pz[3] = {0,0,0}, pr[3] = {0,0,0}, ph[3] = {0,0,0};
#pragma unroll
    for (int q = 0; q < 4; q++) {
        int e = lane + q * 32;
        float hv = hrow[e];
#pragma unroll
        for (int c = 0; c < 3; c++) {
            pz[c] = fmaf(hv, Wpz[e * 3 + c], pz[c]);
            pr[c] = fmaf(hv, Wpr[e * 3 + c], pr[c]);
            ph[c] = fmaf(hv, Wph[e * 3 + c], ph[c]);
        }
    }
#pragma unroll
    for (int off = 16; off; off >>= 1) {
#pragma unroll
        for (int c = 0; c < 3; c++) {
            pz[c] += __shfl_xor_sync(0xffffffffu, pz[c], off);
            pr[c] += __shfl_xor_sync(0xffffffffu, pr[c], off);
            ph[c] += __shfl_xor_sync(0xffffffffu, ph[c], off);
        }
    }
    if (lane == 0) {
        float s0 = gS[node*3+0], s1 = gS[node*3+1], s2 = gS[node*3+2];
        float zs[3], rs[3], ss[3];
#pragma unroll
        for (int c = 0; c < 3; c++)
            zs[c] = sigm(pz[c] + s0*Upz[c] + s1*Upz[3+c] + s2*Upz[6+c] + bpz[c]);
#pragma unroll
        for (int c = 0; c < 3; c++)
            rs[c] = sigm(pr[c] + s0*Upr[c] + s1*Upr[3+c] + s2*Upr[6+c] + bpr[c]);
        float t0 = rs[0]*s0, t1 = rs[1]*s1, t2 = rs[2]*s2;
#pragma unroll
        for (int c = 0; c < 3; c++)
            ss[c] = tanhf(ph[c] + t0*Uph[c] + t1*Uph[3+c] + t2*Uph[6+c] + bph[c]);
        gS[node*3+0] = (1.0f - zs[0])*s0 + zs[0]*ss[0];
        gS[node*3+1] = (1.0f - zs[1])*s1 + zs[1]*ss[1];
        gS[node*3+2] = (1.0f - zs[2])*s2 + zs[2]*ss[2];
    }
}

// ---------------- launch ---------------------------------------------------------
extern "C" void kernel_launch(void* const* d_in, const int* in_sizes, int n_in,
                              void* d_out, int out_size)
{
    const float* x     = (const float*)d_in[0];
    const float* mask  = (const float*)d_in[1];
    const float* W_emb = (const float*)d_in[2];
    const float* b_emb = (const float*)d_in[3];
    const float* pos   = (const float*)d_in[4];
    const float* Wm    = (const float*)d_in[5];
    const float* bm    = (const float*)d_in[6];
    const float* Wz    = (const float*)d_in[7];
    const float* Uz    = (const float*)d_in[8];
    const float* bz    = (const float*)d_in[9];
    const float* Wr    = (const float*)d_in[10];
    const float* Ur    = (const float*)d_in[11];
    const float* br    = (const float*)d_in[12];
    const float* Wh    = (const float*)d_in[13];
    const float* Uh    = (const float*)d_in[14];
    const float* bh    = (const float*)d_in[15];
    const float* Wpz   = (const float*)d_in[16];
    const float* Upz   = (const float*)d_in[17];
    const float* bpz   = (const float*)d_in[18];
    const float* Wpr   = (const float*)d_in[19];
    const float* Upr   = (const float*)d_in[20];
    const float* bpr   = (const float*)d_in[21];
    const float* Wph   = (const float*)d_in[22];
    const float* Uph   = (const float*)d_in[23];
    const float* bph   = (const float*)d_in[24];
    float* Aout = (float*)d_out;

    cudaFuncSetAttribute(mma_gemm<0>, cudaFuncAttributeMaxDynamicSharedMemorySize, SMEM_B);
    cudaFuncSetAttribute(mma_gemm<1>, cudaFuncAttributeMaxDynamicSharedMemorySize, SMEM_B);
    cudaFuncSetAttribute(mma_gemm<2>, cudaFuncAttributeMaxDynamicSharedMemorySize, SMEM_B);
    cudaFuncSetAttribute(mma_gemm<3>, cudaFuncAttributeMaxDynamicSharedMemorySize, SMEM_B);

    __nv_bfloat16 *pAH, *pAL, *pMH, *pML, *phH, *phL, *paH, *paL, *prH, *prL;
    __nv_bfloat16 *pB1H, *pB1L, *pB3H, *pB3L, *pB4H, *pB4L;
    float *pb1, *pb3;
    cudaGetSymbolAddress((void**)&pAH, AHi);   cudaGetSymbolAddress((void**)&pAL, ALo);
    cudaGetSymbolAddress((void**)&pMH, mHi);   cudaGetSymbolAddress((void**)&pML, mLo);
    cudaGetSymbolAddress((void**)&phH, hHi);   cudaGetSymbolAddress((void**)&phL, hLo);
    cudaGetSymbolAddress((void**)&paH, aggHi); cudaGetSymbolAddress((void**)&paL, aggLo);
    cudaGetSymbolAddress((void**)&prH, rhHi);  cudaGetSymbolAddress((void**)&prL, rhLo);
    cudaGetSymbolAddress((void**)&pB1H, B1Hi); cudaGetSymbolAddress((void**)&pB1L, B1Lo);
    cudaGetSymbolAddress((void**)&pB3H, B3Hi); cudaGetSymbolAddress((void**)&pB3L, B3Lo);
    cudaGetSymbolAddress((void**)&pB4H, B4Hi); cudaGetSymbolAddress((void**)&pB4L, B4Lo);
    cudaGetSymbolAddress((void**)&pb1, gB1);   cudaGetSymbolAddress((void**)&pb3, gB3);

    prep_kernel<<<(NITER * 384 * 128 + 255) / 256, 256>>>(Wm, bm, Wz, Uz, bz, Wr, Ur, br, Wh, Uh, bh);
    embed_kernel<<<ROWS, 128>>>(x, W_emb, b_emb, pos);
    init_s_kernel<<<(ROWS + 255) / 256, 256>>>();
    adj_t<0><<<dim3(NN / 8, BSZ), 128>>>(mask, Aout);

    for (int it = 0; it < NITER; it++) {
        // [m | z_pre | r_pre] = h @ [Wm|Uz|Ur]  (B panel [k=128][n=384])
        mma_gemm<1><<<dim3(ROWS / 128, 3, 1), 256, SMEM_B>>>(
            phH, phL, HID, 0,
            pB1H + (size_t)it * 384 * 128, pB1L + (size_t)it * 384 * 128, 384, 0,
            HID, pb1 + it * 384);

        // agg[b] = A[b] @ m[b]   (A symmetric splits, B = m natural [node][hid])
        mma_gemm<0><<<dim3(NN / 128, 1, BSZ), 256, SMEM_B>>>(
            pAH, pAL, NN, (long long)NN * NN,
            pMH, pML, HID, (long long)NN * HID,
            NN, nullptr);

        // [z | r->rh | p] = agg @ [Wz|Wr|Wh] with fused gate epilogues
        mma_gemm<2><<<dim3(ROWS / 128, 3, 1), 256, SMEM_B>>>(
            paH, paL, HID, 0,
            pB3H + (size_t)it * 384 * 128, pB3L + (size_t)it * 384 * 128, 384, 0,
            HID, pb3 + it * 384);

        // h = (1-z) h + z tanh(rh@Uh + p)
        mma_gemm<3><<<dim3(ROWS / 128, 1, 1), 256, SMEM_B>>>(
            prH, prL, HID, 0,
            pB4H + (size_t)it * HID * HID, pB4L + (size_t)it * HID * HID, HID, 0,
            HID, nullptr);

        posgru_kernel<<<ROWS / 8, 256>>>(Wpz, Upz, bpz, Wpr, Upr, bpr, Wph, Uph, bph);

        if (it < NITER - 1)
            adj_t<0><<<dim3(NN / 8, BSZ), 128>>>(mask, Aout);
        else
            adj_t<1><<<dim3(NN / 8, BSZ), 128>>>(mask, Aout);
    }
}

// round 14
// speedup vs baseline: 2.0184x; 1.0006x over previous
#include <cuda_runtime.h>
#include <cuda_bf16.h>
#include <stdint.h>
#include <math.h>

#define BSZ   64
#define NN    512
#define HID   128
#define NITER 3
#define ROWS  (BSZ*NN)

// ---------------- scratch ----------------------------------------------------
__device__ __align__(16) float gH   [ROWS*HID];
__device__ __align__(16) float gZ   [ROWS*HID];
__device__ __align__(16) float gP   [ROWS*HID];
__device__ __align__(16) float gZpre[ROWS*HID];
__device__ __align__(16) float gRpre[ROWS*HID];
__device__ __align__(16) float gS   [ROWS*3];
__device__ __align__(16) __nv_bfloat16 hHi [ROWS*HID], hLo [ROWS*HID];
__device__ __align__(16) __nv_bfloat16 AHi [(size_t)BSZ*NN*NN], ALo [(size_t)BSZ*NN*NN];
__device__ __align__(16) __nv_bfloat16 mHi [ROWS*HID], mLo [ROWS*HID];
__device__ __align__(16) __nv_bfloat16 aggHi[ROWS*HID], aggLo[ROWS*HID];
__device__ __align__(16) __nv_bfloat16 rhHi [ROWS*HID], rhLo [ROWS*HID];
__device__ __align__(16) __nv_bfloat16 B1Hi[NITER*HID*384], B1Lo[NITER*HID*384]; // [k][n]
__device__ __align__(16) __nv_bfloat16 B3Hi[NITER*HID*384], B3Lo[NITER*HID*384]; // [k][n]
__device__ __align__(16) __nv_bfloat16 B4Hi[NITER*HID*HID], B4Lo[NITER*HID*HID]; // [k][n]
__device__ __align__(16) float gB1[NITER*384];
__device__ __align__(16) float gB3[NITER*384];

__device__ __forceinline__ float sigm(float x) { return 1.0f / (1.0f + __expf(-x)); }

__device__ __forceinline__ void split2(float v, __nv_bfloat16& hi, __nv_bfloat16& lo)
{
    __nv_bfloat16 h = __float2bfloat16(v);
    hi = h;
    lo = __float2bfloat16(v - __bfloat162float(h));
}

__device__ __forceinline__ uint32_t smem_u32(const void* p)
{
    uint32_t a;
    asm("{ .reg .u64 t; cvta.to.shared.u64 t, %1; cvt.u32.u64 %0, t; }" : "=r"(a) : "l"(p));
    return a;
}

// ---------------- mma.sync building blocks -----------------------------------
__device__ __forceinline__ void mma16816(float* d, const uint32_t* a, const uint32_t* b)
{
    asm volatile(
        "mma.sync.aligned.m16n8k16.row.col.f32.bf16.bf16.f32 "
        "{%0,%1,%2,%3}, {%4,%5,%6,%7}, {%8,%9}, {%0,%1,%2,%3};"
        : "+f"(d[0]), "+f"(d[1]), "+f"(d[2]), "+f"(d[3])
        : "r"(a[0]), "r"(a[1]), "r"(a[2]), "r"(a[3]), "r"(b[0]), "r"(b[1]));
}

__device__ __forceinline__ void ldsm4(uint32_t* r, uint32_t addr)
{
    asm volatile("ldmatrix.sync.aligned.m8n8.x4.shared.b16 {%0,%1,%2,%3}, [%4];"
                 : "=r"(r[0]), "=r"(r[1]), "=r"(r[2]), "=r"(r[3]) : "r"(addr));
}

__device__ __forceinline__ void ldsm4t(uint32_t* r, uint32_t addr)
{
    asm volatile("ldmatrix.sync.aligned.m8n8.x4.trans.shared.b16 {%0,%1,%2,%3}, [%4];"
                 : "=r"(r[0]), "=r"(r[1]), "=r"(r[2]), "=r"(r[3]) : "r"(addr));
}

__device__ __forceinline__ void cp16(uint32_t s, const void* g)
{
    asm volatile("cp.async.cg.shared.global [%0], [%1], 16;" :: "r"(s), "l"(g));
}

#define ASTRIDE 40                      // bf16 elems per A smem row (32 + 8 pad)
#define BSTRIDE 136                     // bf16 elems per B smem row (128 + 8 pad)
#define A_TILE_B (128*ASTRIDE*2)        // 10240 bytes
#define B_TILE_B (32*BSTRIDE*2)         // 8704 bytes
#define STAGE_B  (2*A_TILE_B + 2*B_TILE_B)   // 37888
#define SMEM_B   (2*STAGE_B)                 // 75776

__device__ __forceinline__ void load_stage(
    uint32_t sb, int buf, int tid, int k0,
    const __nv_bfloat16* Abh, const __nv_bfloat16* Abl, int lda,
    const __nv_bfloat16* Bbh, const __nv_bfloat16* Bbl, int ldb)
{
    uint32_t st = sb + buf * STAGE_B;
    // A tiles: 128 rows x 32 k, hi+lo -> 1024 x 16B chunks
#pragma unroll
    for (int i = 0; i < 4; i++) {
        int id = tid + i * 256;
        int t  = id >> 9;                 // 0 = hi, 1 = lo (uniform per unrolled i)
        int r  = (id >> 2) & 127;
        int c  = id & 3;
        const __nv_bfloat16* g = (t ? Abl : Abh) + (long long)r * lda + k0 + c * 8;
        cp16(st + t * A_TILE_B + r * (ASTRIDE * 2) + c * 16, g);
    }
    // B tiles: 32 k-rows x 128 n, hi+lo -> 1024 x 16B chunks
#pragma unroll
    for (int i = 0; i < 4; i++) {
        int id = tid + i * 256;
        int t  = id >> 9;
        int r  = (id >> 4) & 31;
        int c  = id & 15;
        const __nv_bfloat16* g = (t ? Bbl : Bbh) + (long long)(k0 + r) * ldb + c * 8;
        cp16(st + 2 * A_TILE_B + t * B_TILE_B + r * (BSTRIDE * 2) + c * 16, g);
    }
    asm volatile("cp.async.commit_group;" ::: "memory");
}

// ---------------- split-bf16 tensor-core GEMM (mma.sync) ---------------------
// D[128x128] fp32 = A(hi/lo)[M x K] @ B(hi/lo)[K x N], epilogue from registers.
// EPI 0: agg -> agg splits (batched over bz)
// EPI 1: yy0: m=relu(.+b) -> m splits ; yy1: gZpre ; yy2: gRpre
// EPI 2: yy0: gZ=sigm(.+gZpre) ; yy1: rh=sigm(.+gRpre)*h -> splits ; yy2: gP=.+bh
// EPI 3: h = (1-z) h + z tanh(. + gP) -> gH + h splits
template <int EPI>
__global__ void __launch_bounds__(256)
mma_gemm(const __nv_bfloat16* __restrict__ Ah, const __nv_bfloat16* __restrict__ Al,
         int lda, long long sA,
         const __nv_bfloat16* __restrict__ Bh, const __nv_bfloat16* __restrict__ Bl,
         int ldb, long long sB,
         int K, const float* __restrict__ bias)
{
    extern __shared__ char smem[];
    const uint32_t sb = smem_u32(smem);
    const int tid  = threadIdx.x;
    const int wid  = tid >> 5, lane = tid & 31;
    const int wm   = wid >> 1, wn = wid & 1;          // 4 x 2 warp grid
    const int bm   = blockIdx.x, yy = blockIdx.y, bz = blockIdx.z;

    const __nv_bfloat16* Abh = Ah + bz * sA + (long long)(bm * 128) * lda;
    const __nv_bfloat16* Abl = Al + bz * sA + (long long)(bm * 128) * lda;
    const __nv_bfloat16* Bbh = Bh + bz * sB + yy * 128;
    const __nv_bfloat16* Bbl = Bl + bz * sB + yy * 128;

    float acc[2][8][4];
#pragma unroll
    for (int i = 0; i < 2; i++)
#pragma unroll
        for (int j = 0; j < 8; j++)
#pragma unroll
            for (int e = 0; e < 4; e++) acc[i][j][e] = 0.0f;

    // lane-invariant smem fragment addresses
    const uint32_t aoff = (uint32_t)((wm * 32 + (lane & 15)) * (ASTRIDE * 2) + (lane >> 4) * 16);
    const int q = lane >> 3;
    const uint32_t boff = (uint32_t)(2 * A_TILE_B
                        + ((q & 1) * 8 + (lane & 7)) * (BSTRIDE * 2)
                        + (wn * 64 + (q >> 1) * 8) * 2);

    const int nstage = K >> 5;
    load_stage(sb, 0, tid, 0, Abh, Abl, lda, Bbh, Bbl, ldb);

    for (int kt = 0; kt < nstage; kt++) {
        asm volatile("cp.async.wait_group 0;" ::: "memory");
        __syncthreads();
        if (kt + 1 < nstage)
            load_stage(sb, (kt + 1) & 1, tid, (kt + 1) << 5, Abh, Abl, lda, Bbh, Bbl, ldb);

        const uint32_t st = sb + (kt & 1) * STAGE_B;
#pragma unroll
        for (int j = 0; j < 2; j++) {                 // two k16 per stage
            uint32_t ah[2][4], al[2][4];
#pragma unroll
            for (int mt = 0; mt < 2; mt++) {
                uint32_t a0 = st + aoff + mt * 16 * (ASTRIDE * 2) + j * 32;
                ldsm4(ah[mt], a0);
                ldsm4(al[mt], a0 + A_TILE_B);
            }
#pragma unroll
            for (int np = 0; np < 4; np++) {
                uint32_t bh[4], bl[4];
                uint32_t b0 = st + boff + j * 16 * (BSTRIDE * 2) + np * 32;
                ldsm4t(bh, b0);
                ldsm4t(bl, b0 + B_TILE_B);
#pragma unroll
                for (int mt = 0; mt < 2; mt++) {
                    mma16816(acc[mt][2 * np],     ah[mt], bh);       // hi*hi
                    mma16816(acc[mt][2 * np],     ah[mt], bl);       // hi*lo
                    mma16816(acc[mt][2 * np],     al[mt], bh);       // lo*hi
                    mma16816(acc[mt][2 * np + 1], ah[mt], bh + 2);
                    mma16816(acc[mt][2 * np + 1], ah[mt], bl + 2);
                    mma16816(acc[mt][2 * np + 1], al[mt], bh + 2);
                }
            }
        }
    }

    // ---------------- register epilogue ----------------
    const int lrow = lane >> 2;
    const int lcol = (lane & 3) * 2;
#pragma unroll
    for (int mt = 0; mt < 2; mt++)
#pragma unroll
    for (int nt = 0; nt < 8; nt++)
#pragma unroll
    for (int half = 0; half < 2; half++) {
        const int row = bm * 128 + wm * 32 + mt * 16 + lrow + half * 8;
        const int col = wn * 64 + nt * 8 + lcol;
        float v0 = acc[mt][nt][half * 2 + 0];
        float v1 = acc[mt][nt][half * 2 + 1];

        if (EPI == 0) {
            long long base = ((long long)bz * NN + row) * HID + col;
            __nv_bfloat162 hv, lv;
            split2(v0, hv.x, lv.x); split2(v1, hv.y, lv.y);
            *(__nv_bfloat162*)(aggHi + base) = hv;
            *(__nv_bfloat162*)(aggLo + base) = lv;
        } else if (EPI == 1) {
            int base = row * HID + col;
            if (yy == 0) {
                float m0 = fmaxf(v0 + bias[col],     0.0f);
                float m1 = fmaxf(v1 + bias[col + 1], 0.0f);
                __nv_bfloat162 hv, lv;
                split2(m0, hv.x, lv.x); split2(m1, hv.y, lv.y);
                *(__nv_bfloat162*)(mHi + base) = hv;
                *(__nv_bfloat162*)(mLo + base) = lv;
            } else {
                float* out = (yy == 1) ? gZpre : gRpre;
                float2 o;
                o.x = v0 + bias[yy * 128 + col];
                o.y = v1 + bias[yy * 128 + col + 1];
                *(float2*)(out + base) = o;
            }
        } else if (EPI == 2) {
            int base = row * HID + col;
            if (yy == 0) {
                float2 zp = *(const float2*)(gZpre + base);
                float2 o; o.x = sigm(v0 + zp.x); o.y = sigm(v1 + zp.y);
                *(float2*)(gZ + base) = o;
            } else if (yy == 1) {
                float2 rp = *(const float2*)(gRpre + base);
                float2 hv2 = *(const float2*)(gH + base);
                float rh0 = sigm(v0 + rp.x) * hv2.x;
                float rh1 = sigm(v1 + rp.y) * hv2.y;
                __nv_bfloat162 hv, lv;
                split2(rh0, hv.x, lv.x); split2(rh1, hv.y, lv.y);
                *(__nv_bfloat162*)(rhHi + base) = hv;
                *(__nv_bfloat162*)(rhLo + base) = lv;
            } else {
                float2 o;
                o.x = v0 + bias[256 + col];
                o.y = v1 + bias[256 + col + 1];
                *(float2*)(gP + base) = o;
            }
        } else { // EPI == 3
            int base = row * HID + col;
            float2 z  = *(const float2*)(gZ + base);
            float2 p  = *(const float2*)(gP + base);
            float2 h2 = *(const float2*)(gH + base);
            float hn0 = fmaf(z.x, tanhf(v0 + p.x) - h2.x, h2.x);
            float hn1 = fmaf(z.y, tanhf(v1 + p.y) - h2.y, h2.y);
            float2 o; o.x = hn0; o.y = hn1;
            *(float2*)(gH + base) = o;
            __nv_bfloat162 hv, lv;
            split2(hn0, hv.x, lv.x); split2(hn1, hv.y, lv.y);
            *(__nv_bfloat162*)(hHi + base) = hv;
            *(__nv_bfloat162*)(hLo + base) = lv;
        }
    }
}

// ---------------- weight panel prep ([k][n] natural layout) ------------------
__global__ void prep_kernel(const float* __restrict__ Wm, const float* __restrict__ bm,
                            const float* __restrict__ Wz, const float* __restrict__ Uz, const float* __restrict__ bz,
                            const float* __restrict__ Wr, const float* __restrict__ Ur, const float* __restrict__ br,
                            const float* __restrict__ Wh, const float* __restrict__ Uh, const float* __restrict__ bh)
{
    int idx = blockIdx.x * 256 + threadIdx.x;
    if (idx >= NITER * 384 * 128) return;
    int it  = idx / (384 * 128);
    int rem = idx % (384 * 128);
    int n = rem / 128;            // output channel across 3 panels
    int k = rem % 128;
    int blk = n >> 7, c = n & 127;
    int off = it * HID * HID + k * HID + c;
    float w1 = (blk == 0) ? Wm[off] : (blk == 1 ? Uz[off] : Ur[off]);
    float w3 = (blk == 0) ? Wz[off] : (blk == 1 ? Wr[off] : Wh[off]);
    int po = it * 384 * 128 + k * 384 + n;   // [k][n]
    split2(w1, B1Hi[po], B1Lo[po]);
    split2(w3, B3Hi[po], B3Lo[po]);
    if (blk == 0) {
        int b4 = it * HID * HID + k * 128 + c;   // Uh natural [k][n]
        split2(Uh[off], B4Hi[b4], B4Lo[b4]);
    }
    if (k == 0) {
        gB1[it * 384 + n] = (blk == 0) ? bm[it * HID + c] : (blk == 1 ? bz[it * HID + c] : br[it * HID + c]);
        gB3[it * 384 + n] = (blk == 2) ? bh[it * HID + c] : 0.0f;
    }
}

// ---------------- embedding ---------------------------------------------------
__global__ void embed_kernel(const float* __restrict__ x, const float* __restrict__ W,
                             const float* __restrict__ b, const float* __restrict__ pos)
{
    __shared__ float xs[64];
    int row = blockIdx.x;
    int c = threadIdx.x;
    if (c < 64) xs[c] = x[(size_t)row * 64 + c];
    __syncthreads();
    float acc = b[c];
#pragma unroll 16
    for (int f = 0; f < 64; f++) acc = fmaf(xs[f], W[f * HID + c], acc);
    int n = row & (NN - 1);
    float h = fmaxf(acc, 0.0f) + pos[n * HID + c];
    int o = row * HID + c;
    gH[o] = h;
    split2(h, hHi[o], hLo[o]);
}

__global__ void init_s_kernel()
{
    int idx = blockIdx.x * blockDim.x + threadIdx.x;
    if (idx < ROWS) {
        int j = idx & (NN - 1);
        gS[idx * 3 + 0] = (j - 255.5f) * (1.0f / NN);
        gS[idx * 3 + 1] = 0.0f;
        gS[idx * 3 + 2] = 0.0f;
    }
}

// ---------------- adjacency: MODE 0 -> bf16 splits, MODE 1 -> fp32 d_out ------
template <int MODE>
__global__ void adj_t(const float* __restrict__ mask, float* __restrict__ Aout)
{
    int b  = blockIdx.y;
    int i0 = blockIdx.x * 8;
    __shared__ float sx[NN], sy[NN], sz[NN];
    const float* s = gS + (size_t)b * NN * 3;
    for (int j = threadIdx.x; j < NN; j += 128) {
        sx[j] = s[j * 3 + 0]; sy[j] = s[j * 3 + 1]; sz[j] = s[j * 3 + 2];
    }
    __syncthreads();
    int j0 = threadIdx.x * 4;
#pragma unroll
    for (int rr = 0; rr < 8; rr++) {
        int i = i0 + rr;
        float xi = sx[i], yi = sy[i], zi = sz[i];
        size_t base = ((size_t)b * NN + i) * NN + j0;
        float4 mv = *(const float4*)(mask + base);
        float a[4];
#pragma unroll
        for (int t = 0; t < 4; t++) {
            int j = j0 + t;
            float dx = xi - sx[j], dy = yi - sy[j], dz = zi - sz[j];
            a[t] = __expf(-100.0f * (dx * dx + dy * dy + dz * dz)) * ((&mv.x)[t]);
        }
        if (MODE == 1) {
            float4 ov; ov.x = a[0]; ov.y = a[1]; ov.z = a[2]; ov.w = a[3];
            *(float4*)(Aout + base) = ov;
        } else {
            __nv_bfloat16 h2[4], l2[4];
#pragma unroll
            for (int t = 0; t < 4; t++) split2(a[t], h2[t], l2[t]);
            __nv_bfloat162 p0; p0.x = h2[0]; p0.y = h2[1];
            __nv_bfloat162 p1; p1.x = h2[2]; p1.y = h2[3];
            __nv_bfloat162 q0; q0.x = l2[0]; q0.y = l2[1];
            __nv_bfloat162 q1; q1.x = l2[2]; q1.y = l2[3];
            *(__nv_bfloat162*)(AHi + base)     = p0;
            *(__nv_bfloat162*)(AHi + base + 2) = p1;
            *(__nv_bfloat162*)(ALo + base)     = q0;
            *(__nv_bfloat162*)(ALo + base + 2) = q1;
        }
    }
}

// ---------------- positional GRU ------------------------------------------------
__global__ void posgru_kernel(const float* __restrict__ Wpz, const float* __restrict__ Upz, const float* __restrict__ bpz,
                              const float* __restrict__ Wpr, const float* __restrict__ Upr, const float* __restrict__ bpr,
                              const float* __restrict__ Wph, const float* __restrict__ Uph, const float* __restrict__ bph)
{
    int gtid = blockIdx.x * blockDim.x + threadIdx.x;
    int node = gtid >> 5;
    int lane = threadIdx.x & 31;
    if (node >= ROWS) return;
    const float* hrow = gH + (size_t)node * HID;
    float pz[3] = {0,0,0}, pr[3] = {0,0,0}, ph[3] = {0,0,0};
#pragma unroll
    for (int q = 0; q < 4; q++) {
        int e = lane + q * 32;
        float hv = hrow[e];
#pragma unroll
        for (int c = 0; c < 3; c++) {
            pz[c] = fmaf(hv, Wpz[e * 3 + c], pz[c]);
            pr[c] = fmaf(hv, Wpr[e * 3 + c], pr[c]);
            ph[c] = fmaf(hv, Wph[e * 3 + c], ph[c]);
        }
    }
#pragma unroll
    for (int off = 16; off; off >>= 1) {
#pragma unroll
        for (int c = 0; c < 3; c++) {
            pz[c] += __shfl_xor_sync(0xffffffffu, pz[c], off);
            pr[c] += __shfl_xor_sync(0xffffffffu, pr[c], off);
            ph[c] += __shfl_xor_sync(0xffffffffu, ph[c], off);
        }
    }
    if (lane == 0) {
        float s0 = gS[node*3+0], s1 = gS[node*3+1], s2 = gS[node*3+2];
        float zs[3], rs[3], ss[3];
#pragma unroll
        for (int c = 0; c < 3; c++)
            zs[c] = sigm(pz[c] + s0*Upz[c] + s1*Upz[3+c] + s2*Upz[6+c] + bpz[c]);
#pragma unroll
        for (int c = 0; c < 3; c++)
            rs[c] = sigm(pr[c] + s0*Upr[c] + s1*Upr[3+c] + s2*Upr[6+c] + bpr[c]);
        float t0 = rs[0]*s0, t1 = rs[1]*s1, t2 = rs[2]*s2;
#pragma unroll
        for (int c = 0; c < 3; c++)
            ss[c] = tanhf(ph[c] + t0*Uph[c] + t1*Uph[3+c] + t2*Uph[6+c] + bph[c]);
        gS[node*3+0] = (1.0f - zs[0])*s0 + zs[0]*ss[0];
        gS[node*3+1] = (1.0f - zs[1])*s1 + zs[1]*ss[1];
        gS[node*3+2] = (1.0f - zs[2])*s2 + zs[2]*ss[2];
    }
}

// ---------------- launch ---------------------------------------------------------
extern "C" void kernel_launch(void* const* d_in, const int* in_sizes, int n_in,
                              void* d_out, int out_size)
{
    const float* x     = (const float*)d_in[0];
    const float* mask  = (const float*)d_in[1];
    const float* W_emb = (const float*)d_in[2];
    const float* b_emb = (const float*)d_in[3];
    const float* pos   = (const float*)d_in[4];
    const float* Wm    = (const float*)d_in[5];
    const float* bm    = (const float*)d_in[6];
    const float* Wz    = (const float*)d_in[7];
    const float* Uz    = (const float*)d_in[8];
    const float* bz    = (const float*)d_in[9];
    const float* Wr    = (const float*)d_in[10];
    const float* Ur    = (const float*)d_in[11];
    const float* br    = (const float*)d_in[12];
    const float* Wh    = (const float*)d_in[13];
    const float* Uh    = (const float*)d_in[14];
    const float* bh    = (const float*)d_in[15];
    const float* Wpz   = (const float*)d_in[16];
    const float* Upz   = (const float*)d_in[17];
    const float* bpz   = (const float*)d_in[18];
    const float* Wpr   = (const float*)d_in[19];
    const float* Upr   = (const float*)d_in[20];
    const float* bpr   = (const float*)d_in[21];
    const float* Wph   = (const float*)d_in[22];
    const float* Uph   = (const float*)d_in[23];
    const float* bph   = (const float*)d_in[24];
    float* Aout = (float*)d_out;

    cudaFuncSetAttribute(mma_gemm<0>, cudaFuncAttributeMaxDynamicSharedMemorySize, SMEM_B);
    cudaFuncSetAttribute(mma_gemm<1>, cudaFuncAttributeMaxDynamicSharedMemorySize, SMEM_B);
    cudaFuncSetAttribute(mma_gemm<2>, cudaFuncAttributeMaxDynamicSharedMemorySize, SMEM_B);
    cudaFuncSetAttribute(mma_gemm<3>, cudaFuncAttributeMaxDynamicSharedMemorySize, SMEM_B);

    __nv_bfloat16 *pAH, *pAL, *pMH, *pML, *phH, *phL, *paH, *paL, *prH, *prL;
    __nv_bfloat16 *pB1H, *pB1L, *pB3H, *pB3L, *pB4H, *pB4L;
    float *pb1, *pb3;
    cudaGetSymbolAddress((void**)&pAH, AHi);   cudaGetSymbolAddress((void**)&pAL, ALo);
    cudaGetSymbolAddress((void**)&pMH, mHi);   cudaGetSymbolAddress((void**)&pML, mLo);
    cudaGetSymbolAddress((void**)&phH, hHi);   cudaGetSymbolAddress((void**)&phL, hLo);
    cudaGetSymbolAddress((void**)&paH, aggHi); cudaGetSymbolAddress((void**)&paL, aggLo);
    cudaGetSymbolAddress((void**)&prH, rhHi);  cudaGetSymbolAddress((void**)&prL, rhLo);
    cudaGetSymbolAddress((void**)&pB1H, B1Hi); cudaGetSymbolAddress((void**)&pB1L, B1Lo);
    cudaGetSymbolAddress((void**)&pB3H, B3Hi); cudaGetSymbolAddress((void**)&pB3L, B3Lo);
    cudaGetSymbolAddress((void**)&pB4H, B4Hi); cudaGetSymbolAddress((void**)&pB4L, B4Lo);
    cudaGetSymbolAddress((void**)&pb1, gB1);   cudaGetSymbolAddress((void**)&pb3, gB3);

    prep_kernel<<<(NITER * 384 * 128 + 255) / 256, 256>>>(Wm, bm, Wz, Uz, bz, Wr, Ur, br, Wh, Uh, bh);
    embed_kernel<<<ROWS, 128>>>(x, W_emb, b_emb, pos);
    init_s_kernel<<<(ROWS + 255) / 256, 256>>>();
    adj_t<0><<<dim3(NN / 8, BSZ), 128>>>(mask, Aout);

    for (int it = 0; it < NITER; it++) {
        // [m | z_pre | r_pre] = h @ [Wm|Uz|Ur]  (B panel [k=128][n=384])
        mma_gemm<1><<<dim3(ROWS / 128, 3, 1), 256, SMEM_B>>>(
            phH, phL, HID, 0,
            pB1H + (size_t)it * 384 * 128, pB1L + (size_t)it * 384 * 128, 384, 0,
            HID, pb1 + it * 384);

        // agg[b] = A[b] @ m[b]   (A symmetric splits, B = m natural [node][hid])
        mma_gemm<0><<<dim3(NN / 128, 1, BSZ), 256, SMEM_B>>>(
            pAH, pAL, NN, (long long)NN * NN,
            pMH, pML, HID, (long long)NN * HID,
            NN, nullptr);

        // [z | r->rh | p] = agg @ [Wz|Wr|Wh] with fused gate epilogues
        mma_gemm<2><<<dim3(ROWS / 128, 3, 1), 256, SMEM_B>>>(
            paH, paL, HID, 0,
            pB3H + (size_t)it * 384 * 128, pB3L + (size_t)it * 384 * 128, 384, 0,
            HID, pb3 + it * 384);

        // h = (1-z) h + z tanh(rh@Uh + p)
        mma_gemm<3><<<dim3(ROWS / 128, 1, 1), 256, SMEM_B>>>(
            prH, prL, HID, 0,
            pB4H + (size_t)it * HID * HID, pB4L + (size_t)it * HID * HID, HID, 0,
            HID, nullptr);

        posgru_kernel<<<ROWS / 8, 256>>>(Wpz, Upz, bpz, Wpr, Upr, bpr, Wph, Uph, bph);

        if (it < NITER - 1)
            adj_t<0><<<dim3(NN / 8, BSZ), 128>>>(mask, Aout);
        else
            adj_t<1><<<dim3(NN / 8, BSZ), 128>>>(mask, Aout);
    }
}

// round 15
// speedup vs baseline: 2.0991x; 1.0400x over previous
#include <cuda_runtime.h>
#include <cuda_bf16.h>
#include <stdint.h>
#include <math.h>

#define BSZ   64
#define NN    512
#define HID   128
#define NITER 3
#define ROWS  (BSZ*NN)

// ---------------- scratch ----------------------------------------------------
__device__ __align__(16) float gH   [ROWS*HID];
__device__ __align__(16) float gZ   [ROWS*HID];
__device__ __align__(16) float gP   [ROWS*HID];
__device__ __align__(16) float gZpre[ROWS*HID];
__device__ __align__(16) float gRpre[ROWS*HID];
__device__ __align__(16) float gS   [ROWS*3];
__device__ __align__(16) __nv_bfloat16 hHi [ROWS*HID], hLo [ROWS*HID];
__device__ __align__(16) __nv_bfloat16 AHi [(size_t)BSZ*NN*NN], ALo [(size_t)BSZ*NN*NN];
__device__ __align__(16) __nv_bfloat16 mHi [ROWS*HID], mLo [ROWS*HID];
__device__ __align__(16) __nv_bfloat16 aggHi[ROWS*HID], aggLo[ROWS*HID];
__device__ __align__(16) __nv_bfloat16 rhHi [ROWS*HID], rhLo [ROWS*HID];
__device__ __align__(16) __nv_bfloat16 B1Hi[NITER*HID*384], B1Lo[NITER*HID*384]; // [k][n]
__device__ __align__(16) __nv_bfloat16 B3Hi[NITER*HID*384], B3Lo[NITER*HID*384]; // [k][n]
__device__ __align__(16) __nv_bfloat16 B4Hi[NITER*HID*HID], B4Lo[NITER*HID*HID]; // [k][n]
__device__ __align__(16) float gB1[NITER*384];
__device__ __align__(16) float gB3[NITER*384];

struct PosW { const float* p[9]; };   // Wpz,Upz,bpz, Wpr,Upr,bpr, Wph,Uph,bph

__device__ __forceinline__ float sigm(float x) { return 1.0f / (1.0f + __expf(-x)); }

__device__ __forceinline__ void split2(float v, __nv_bfloat16& hi, __nv_bfloat16& lo)
{
    __nv_bfloat16 h = __float2bfloat16(v);
    hi = h;
    lo = __float2bfloat16(v - __bfloat162float(h));
}

__device__ __forceinline__ uint32_t smem_u32(const void* p)
{
    uint32_t a;
    asm("{ .reg .u64 t; cvta.to.shared.u64 t, %1; cvt.u32.u64 %0, t; }" : "=r"(a) : "l"(p));
    return a;
}

// ---------------- mma.sync building blocks -----------------------------------
__device__ __forceinline__ void mma16816(float* d, const uint32_t* a, const uint32_t* b)
{
    asm volatile(
        "mma.sync.aligned.m16n8k16.row.col.f32.bf16.bf16.f32 "
        "{%0,%1,%2,%3}, {%4,%5,%6,%7}, {%8,%9}, {%0,%1,%2,%3};"
        : "+f"(d[0]), "+f"(d[1]), "+f"(d[2]), "+f"(d[3])
        : "r"(a[0]), "r"(a[1]), "r"(a[2]), "r"(a[3]), "r"(b[0]), "r"(b[1]));
}

__device__ __forceinline__ void ldsm4(uint32_t* r, uint32_t addr)
{
    asm volatile("ldmatrix.sync.aligned.m8n8.x4.shared.b16 {%0,%1,%2,%3}, [%4];"
                 : "=r"(r[0]), "=r"(r[1]), "=r"(r[2]), "=r"(r[3]) : "r"(addr));
}

__device__ __forceinline__ void ldsm4t(uint32_t* r, uint32_t addr)
{
    asm volatile("ldmatrix.sync.aligned.m8n8.x4.trans.shared.b16 {%0,%1,%2,%3}, [%4];"
                 : "=r"(r[0]), "=r"(r[1]), "=r"(r[2]), "=r"(r[3]) : "r"(addr));
}

__device__ __forceinline__ void cp16(uint32_t s, const void* g)
{
    asm volatile("cp.async.cg.shared.global [%0], [%1], 16;" :: "r"(s), "l"(g));
}

#define ASTRIDE 40                      // bf16 elems per A smem row (32 + 8 pad)
#define BSTRIDE 136                     // bf16 elems per B smem row (128 + 8 pad)
#define A_TILE_B (128*ASTRIDE*2)        // 10240 bytes
#define B_TILE_B (32*BSTRIDE*2)         // 8704 bytes
#define STAGE_B  (2*A_TILE_B + 2*B_TILE_B)   // 37888
#define SMEM_B   (2*STAGE_B)                 // 75776

__device__ __forceinline__ void load_stage(
    uint32_t sb, int buf, int tid, int k0,
    const __nv_bfloat16* Abh, const __nv_bfloat16* Abl, int lda,
    const __nv_bfloat16* Bbh, const __nv_bfloat16* Bbl, int ldb)
{
    uint32_t st = sb + buf * STAGE_B;
#pragma unroll
    for (int i = 0; i < 4; i++) {
        int id = tid + i * 256;
        int t  = id >> 9;
        int r  = (id >> 2) & 127;
        int c  = id & 3;
        const __nv_bfloat16* g = (t ? Abl : Abh) + (long long)r * lda + k0 + c * 8;
        cp16(st + t * A_TILE_B + r * (ASTRIDE * 2) + c * 16, g);
    }
#pragma unroll
    for (int i = 0; i < 4; i++) {
        int id = tid + i * 256;
        int t  = id >> 9;
        int r  = (id >> 4) & 31;
        int c  = id & 15;
        const __nv_bfloat16* g = (t ? Bbl : Bbh) + (long long)(k0 + r) * ldb + c * 8;
        cp16(st + 2 * A_TILE_B + t * B_TILE_B + r * (BSTRIDE * 2) + c * 16, g);
    }
    asm volatile("cp.async.commit_group;" ::: "memory");
}

// ---------------- split-bf16 tensor-core GEMM (mma.sync) ---------------------
// EPI 0: agg -> agg splits (batched over bz)
// EPI 1: yy0: m=relu(.+b) -> m splits ; yy1: gZpre ; yy2: gRpre
// EPI 2: yy0: gZ=sigm(.+gZpre) ; yy1: rh=sigm(.+gRpre)*h -> splits ; yy2: gP=.+bh
// EPI 3: h = (1-z) h + z tanh(. + gP) -> gH + h splits, then FUSED posgru
template <int EPI>
__global__ void __launch_bounds__(256, 2)
mma_gemm(const __nv_bfloat16* __restrict__ Ah, const __nv_bfloat16* __restrict__ Al,
         int lda, long long sA,
         const __nv_bfloat16* __restrict__ Bh, const __nv_bfloat16* __restrict__ Bl,
         int ldb, long long sB,
         int K, const float* __restrict__ bias, PosW pw)
{
    extern __shared__ char smem[];
    const uint32_t sb = smem_u32(smem);
    const int tid  = threadIdx.x;
    const int wid  = tid >> 5, lane = tid & 31;
    const int wm   = wid >> 1, wn = wid & 1;          // 4 x 2 warp grid
    const int bm   = blockIdx.x, yy = blockIdx.y, bz = blockIdx.z;

    const __nv_bfloat16* Abh = Ah + bz * sA + (long long)(bm * 128) * lda;
    const __nv_bfloat16* Abl = Al + bz * sA + (long long)(bm * 128) * lda;
    const __nv_bfloat16* Bbh = Bh + bz * sB + yy * 128;
    const __nv_bfloat16* Bbl = Bl + bz * sB + yy * 128;

    float acc[2][8][4];
#pragma unroll
    for (int i = 0; i < 2; i++)
#pragma unroll
        for (int j = 0; j < 8; j++)
#pragma unroll
            for (int e = 0; e < 4; e++) acc[i][j][e] = 0.0f;

    const uint32_t aoff = (uint32_t)((wm * 32 + (lane & 15)) * (ASTRIDE * 2) + (lane >> 4) * 16);
    const int q = lane >> 3;
    const uint32_t boff = (uint32_t)(2 * A_TILE_B
                        + ((q & 1) * 8 + (lane & 7)) * (BSTRIDE * 2)
                        + (wn * 64 + (q >> 1) * 8) * 2);

    const int nstage = K >> 5;
    load_stage(sb, 0, tid, 0, Abh, Abl, lda, Bbh, Bbl, ldb);

    for (int kt = 0; kt < nstage; kt++) {
        asm volatile("cp.async.wait_group 0;" ::: "memory");
        __syncthreads();
        if (kt + 1 < nstage)
            load_stage(sb, (kt + 1) & 1, tid, (kt + 1) << 5, Abh, Abl, lda, Bbh, Bbl, ldb);

        const uint32_t st = sb + (kt & 1) * STAGE_B;
#pragma unroll
        for (int j = 0; j < 2; j++) {
            uint32_t ah[2][4], al[2][4];
#pragma unroll
            for (int mt = 0; mt < 2; mt++) {
                uint32_t a0 = st + aoff + mt * 16 * (ASTRIDE * 2) + j * 32;
                ldsm4(ah[mt], a0);
                ldsm4(al[mt], a0 + A_TILE_B);
            }
#pragma unroll
            for (int np = 0; np < 4; np++) {
                uint32_t bh[4], bl[4];
                uint32_t b0 = st + boff + j * 16 * (BSTRIDE * 2) + np * 32;
                ldsm4t(bh, b0);
                ldsm4t(bl, b0 + B_TILE_B);
#pragma unroll
                for (int mt = 0; mt < 2; mt++) {
                    mma16816(acc[mt][2 * np],     ah[mt], bh);
                    mma16816(acc[mt][2 * np],     ah[mt], bl);
                    mma16816(acc[mt][2 * np],     al[mt], bh);
                    mma16816(acc[mt][2 * np + 1], ah[mt], bh + 2);
                    mma16816(acc[mt][2 * np + 1], ah[mt], bl + 2);
                    mma16816(acc[mt][2 * np + 1], al[mt], bh + 2);
                }
            }
        }
    }

    // EPI3 stages fresh h into smem (pipeline buffers are dead after this sync)
    float* hs = (float*)smem;          // 128 x 128 fp32 = 64 KB <= 75776
    if (EPI == 3) __syncthreads();

    // ---------------- register epilogue ----------------
    const int lrow = lane >> 2;
    const int lcol = (lane & 3) * 2;
#pragma unroll
    for (int mt = 0; mt < 2; mt++)
#pragma unroll
    for (int nt = 0; nt < 8; nt++)
#pragma unroll
    for (int half = 0; half < 2; half++) {
        const int rloc = wm * 32 + mt * 16 + lrow + half * 8;
        const int row = bm * 128 + rloc;
        const int col = wn * 64 + nt * 8 + lcol;
        float v0 = acc[mt][nt][half * 2 + 0];
        float v1 = acc[mt][nt][half * 2 + 1];

        if (EPI == 0) {
            long long base = ((long long)bz * NN + row) * HID + col;
            __nv_bfloat162 hv, lv;
            split2(v0, hv.x, lv.x); split2(v1, hv.y, lv.y);
            *(__nv_bfloat162*)(aggHi + base) = hv;
            *(__nv_bfloat162*)(aggLo + base) = lv;
        } else if (EPI == 1) {
            int base = row * HID + col;
            if (yy == 0) {
                float m0 = fmaxf(v0 + bias[col],     0.0f);
                float m1 = fmaxf(v1 + bias[col + 1], 0.0f);
                __nv_bfloat162 hv, lv;
                split2(m0, hv.x, lv.x); split2(m1, hv.y, lv.y);
                *(__nv_bfloat162*)(mHi + base) = hv;
                *(__nv_bfloat162*)(mLo + base) = lv;
            } else {
                float* out = (yy == 1) ? gZpre : gRpre;
                float2 o;
                o.x = v0 + bias[yy * 128 + col];
                o.y = v1 + bias[yy * 128 + col + 1];
                *(float2*)(out + base) = o;
            }
        } else if (EPI == 2) {
            int base = row * HID + col;
            if (yy == 0) {
                float2 zp = *(const float2*)(gZpre + base);
                float2 o; o.x = sigm(v0 + zp.x); o.y = sigm(v1 + zp.y);
                *(float2*)(gZ + base) = o;
            } else if (yy == 1) {
                float2 rp = *(const float2*)(gRpre + base);
                float2 hv2 = *(const float2*)(gH + base);
                float rh0 = sigm(v0 + rp.x) * hv2.x;
                float rh1 = sigm(v1 + rp.y) * hv2.y;
                __nv_bfloat162 hv, lv;
                split2(rh0, hv.x, lv.x); split2(rh1, hv.y, lv.y);
                *(__nv_bfloat162*)(rhHi + base) = hv;
                *(__nv_bfloat162*)(rhLo + base) = lv;
            } else {
                float2 o;
                o.x = v0 + bias[256 + col];
                o.y = v1 + bias[256 + col + 1];
                *(float2*)(gP + base) = o;
            }
        } else { // EPI == 3
            int base = row * HID + col;
            float2 z  = *(const float2*)(gZ + base);
            float2 p  = *(const float2*)(gP + base);
            float2 h2 = *(const float2*)(gH + base);
            float hn0 = fmaf(z.x, tanhf(v0 + p.x) - h2.x, h2.x);
            float hn1 = fmaf(z.y, tanhf(v1 + p.y) - h2.y, h2.y);
            float2 o; o.x = hn0; o.y = hn1;
            *(float2*)(gH + base) = o;
            hs[rloc * HID + col]     = hn0;
            hs[rloc * HID + col + 1] = hn1;
            __nv_bfloat162 hv, lv;
            split2(hn0, hv.x, lv.x); split2(hn1, hv.y, lv.y);
            *(__nv_bfloat162*)(hHi + base) = hv;
            *(__nv_bfloat162*)(hLo + base) = lv;
        }
    }

    // ---------------- fused positional GRU (EPI 3 only) ----------------
    if (EPI == 3) {
        __syncthreads();
        const float* Wpz = pw.p[0]; const float* Upz = pw.p[1]; const float* bpz = pw.p[2];
        const float* Wpr = pw.p[3]; const float* Upr = pw.p[4]; const float* bpr = pw.p[5];
        const float* Wph = pw.p[6]; const float* Uph = pw.p[7]; const float* bph = pw.p[8];
#pragma unroll 1
        for (int t = 0; t < 16; t++) {
            const int nloc = wid * 16 + t;
            const int node = bm * 128 + nloc;
            const float* hrow = hs + nloc * HID;
            float pz[3] = {0,0,0}, pr[3] = {0,0,0}, ph[3] = {0,0,0};
#pragma unroll
            for (int qq = 0; qq < 4; qq++) {
                int e = lane + qq * 32;
                float hv = hrow[e];
#pragma unroll
                for (int c = 0; c < 3; c++) {
                    pz[c] = fmaf(hv, Wpz[e * 3 + c], pz[c]);
                    pr[c] = fmaf(hv, Wpr[e * 3 + c], pr[c]);
                    ph[c] = fmaf(hv, Wph[e * 3 + c], ph[c]);
                }
            }
#pragma unroll
            for (int off = 16; off; off >>= 1) {
#pragma unroll
                for (int c = 0; c < 3; c++) {
                    pz[c] += __shfl_xor_sync(0xffffffffu, pz[c], off);
                    pr[c] += __shfl_xor_sync(0xffffffffu, pr[c], off);
                    ph[c] += __shfl_xor_sync(0xffffffffu, ph[c], off);
                }
            }
            if (lane == 0) {
                float s0 = gS[node*3+0], s1 = gS[node*3+1], s2 = gS[node*3+2];
                float zs[3], rs[3], ss[3];
#pragma unroll
                for (int c = 0; c < 3; c++)
                    zs[c] = sigm(pz[c] + s0*Upz[c] + s1*Upz[3+c] + s2*Upz[6+c] + bpz[c]);
#pragma unroll
                for (int c = 0; c < 3; c++)
                    rs[c] = sigm(pr[c] + s0*Upr[c] + s1*Upr[3+c] + s2*Upr[6+c] + bpr[c]);
                float t0 = rs[0]*s0, t1 = rs[1]*s1, t2 = rs[2]*s2;
#pragma unroll
                for (int c = 0; c < 3; c++)
                    ss[c] = tanhf(ph[c] + t0*Uph[c] + t1*Uph[3+c] + t2*Uph[6+c] + bph[c]);
                gS[node*3+0] = (1.0f - zs[0])*s0 + zs[0]*ss[0];
                gS[node*3+1] = (1.0f - zs[1])*s1 + zs[1]*ss[1];
                gS[node*3+2] = (1.0f - zs[2])*s2 + zs[2]*ss[2];
            }
        }
    }
}

// ---------------- weight panel prep ([k][n] natural layout) ------------------
__global__ void prep_kernel(const float* __restrict__ Wm, const float* __restrict__ bm,
                            const float* __restrict__ Wz, const float* __restrict__ Uz, const float* __restrict__ bz,
                            const float* __restrict__ Wr, const float* __restrict__ Ur, const float* __restrict__ br,
                            const float* __restrict__ Wh, const float* __restrict__ Uh, const float* __restrict__ bh)
{
    int idx = blockIdx.x * 256 + threadIdx.x;
    if (idx >= NITER * 384 * 128) return;
    int it  = idx / (384 * 128);
    int rem = idx % (384 * 128);
    int n = rem / 128;
    int k = rem % 128;
    int blk = n >> 7, c = n & 127;
    int off = it * HID * HID + k * HID + c;
    float w1 = (blk == 0) ? Wm[off] : (blk == 1 ? Uz[off] : Ur[off]);
    float w3 = (blk == 0) ? Wz[off] : (blk == 1 ? Wr[off] : Wh[off]);
    int po = it * 384 * 128 + k * 384 + n;
    split2(w1, B1Hi[po], B1Lo[po]);
    split2(w3, B3Hi[po], B3Lo[po]);
    if (blk == 0) {
        int b4 = it * HID * HID + k * 128 + c;
        split2(Uh[off], B4Hi[b4], B4Lo[b4]);
    }
    if (k == 0) {
        gB1[it * 384 + n] = (blk == 0) ? bm[it * HID + c] : (blk == 1 ? bz[it * HID + c] : br[it * HID + c]);
        gB3[it * 384 + n] = (blk == 2) ? bh[it * HID + c] : 0.0f;
    }
}

// ---------------- embedding ---------------------------------------------------
__global__ void embed_kernel(const float* __restrict__ x, const float* __restrict__ W,
                             const float* __restrict__ b, const float* __restrict__ pos)
{
    __shared__ float xs[64];
    int row = blockIdx.x;
    int c = threadIdx.x;
    if (c < 64) xs[c] = x[(size_t)row * 64 + c];
    __syncthreads();
    float acc = b[c];
#pragma unroll 16
    for (int f = 0; f < 64; f++) acc = fmaf(xs[f], W[f * HID + c], acc);
    int n = row & (NN - 1);
    float h = fmaxf(acc, 0.0f) + pos[n * HID + c];
    int o = row * HID + c;
    gH[o] = h;
    split2(h, hHi[o], hLo[o]);
}

__global__ void init_s_kernel()
{
    int idx = blockIdx.x * blockDim.x + threadIdx.x;
    if (idx < ROWS) {
        int j = idx & (NN - 1);
        gS[idx * 3 + 0] = (j - 255.5f) * (1.0f / NN);
        gS[idx * 3 + 1] = 0.0f;
        gS[idx * 3 + 2] = 0.0f;
    }
}

// ---------------- adjacency: MODE 0 -> bf16 splits, MODE 1 -> fp32 d_out ------
template <int MODE>
__global__ void adj_t(const float* __restrict__ mask, float* __restrict__ Aout)
{
    int b  = blockIdx.y;
    int i0 = blockIdx.x * 8;
    __shared__ float sx[NN], sy[NN], sz[NN];
    const float* s = gS + (size_t)b * NN * 3;
    for (int j = threadIdx.x; j < NN; j += 128) {
        sx[j] = s[j * 3 + 0]; sy[j] = s[j * 3 + 1]; sz[j] = s[j * 3 + 2];
    }
    __syncthreads();
    int j0 = threadIdx.x * 4;
#pragma unroll
    for (int rr = 0; rr < 8; rr++) {
        int i = i0 + rr;
        float xi = sx[i], yi = sy[i], zi = sz[i];
        size_t base = ((size_t)b * NN + i) * NN + j0;
        float4 mv = *(const float4*)(mask + base);
        float a[4];
#pragma unroll
        for (int t = 0; t < 4; t++) {
            int j = j0 + t;
            float dx = xi - sx[j], dy = yi - sy[j], dz = zi - sz[j];
            a[t] = __expf(-100.0f * (dx * dx + dy * dy + dz * dz)) * ((&mv.x)[t]);
        }
        if (MODE == 1) {
            float4 ov; ov.x = a[0]; ov.y = a[1]; ov.z = a[2]; ov.w = a[3];
            *(float4*)(Aout + base) = ov;
        } else {
            __nv_bfloat16 h2[4], l2[4];
#pragma unroll
            for (int t = 0; t < 4; t++) split2(a[t], h2[t], l2[t]);
            __nv_bfloat162 p0; p0.x = h2[0]; p0.y = h2[1];
            __nv_bfloat162 p1; p1.x = h2[2]; p1.y = h2[3];
            __nv_bfloat162 q0; q0.x = l2[0]; q0.y = l2[1];
            __nv_bfloat162 q1; q1.x = l2[2]; q1.y = l2[3];
            *(__nv_bfloat162*)(AHi + base)     = p0;
            *(__nv_bfloat162*)(AHi + base + 2) = p1;
            *(__nv_bfloat162*)(ALo + base)     = q0;
            *(__nv_bfloat162*)(ALo + base + 2) = q1;
        }
    }
}

// ---------------- launch ---------------------------------------------------------
extern "C" void kernel_launch(void* const* d_in, const int* in_sizes, int n_in,
                              void* d_out, int out_size)
{
    const float* x     = (const float*)d_in[0];
    const float* mask  = (const float*)d_in[1];
    const float* W_emb = (const float*)d_in[2];
    const float* b_emb = (const float*)d_in[3];
    const float* pos   = (const float*)d_in[4];
    const float* Wm    = (const float*)d_in[5];
    const float* bm    = (const float*)d_in[6];
    const float* Wz    = (const float*)d_in[7];
    const float* Uz    = (const float*)d_in[8];
    const float* bz    = (const float*)d_in[9];
    const float* Wr    = (const float*)d_in[10];
    const float* Ur    = (const float*)d_in[11];
    const float* br    = (const float*)d_in[12];
    const float* Wh    = (const float*)d_in[13];
    const float* Uh    = (const float*)d_in[14];
    const float* bh    = (const float*)d_in[15];
    PosW pw;
    for (int i = 0; i < 9; i++) pw.p[i] = (const float*)d_in[16 + i];
    float* Aout = (float*)d_out;
    PosW pw0 = pw;   // same payload for all EPIs (ignored unless EPI==3)

    cudaFuncSetAttribute(mma_gemm<0>, cudaFuncAttributeMaxDynamicSharedMemorySize, SMEM_B);
    cudaFuncSetAttribute(mma_gemm<1>, cudaFuncAttributeMaxDynamicSharedMemorySize, SMEM_B);
    cudaFuncSetAttribute(mma_gemm<2>, cudaFuncAttributeMaxDynamicSharedMemorySize, SMEM_B);
    cudaFuncSetAttribute(mma_gemm<3>, cudaFuncAttributeMaxDynamicSharedMemorySize, SMEM_B);

    __nv_bfloat16 *pAH, *pAL, *pMH, *pML, *phH, *phL, *paH, *paL, *prH, *prL;
    __nv_bfloat16 *pB1H, *pB1L, *pB3H, *pB3L, *pB4H, *pB4L;
    float *pb1, *pb3;
    cudaGetSymbolAddress((void**)&pAH, AHi);   cudaGetSymbolAddress((void**)&pAL, ALo);
    cudaGetSymbolAddress((void**)&pMH, mHi);   cudaGetSymbolAddress((void**)&pML, mLo);
    cudaGetSymbolAddress((void**)&phH, hHi);   cudaGetSymbolAddress((void**)&phL, hLo);
    cudaGetSymbolAddress((void**)&paH, aggHi); cudaGetSymbolAddress((void**)&paL, aggLo);
    cudaGetSymbolAddress((void**)&prH, rhHi);  cudaGetSymbolAddress((void**)&prL, rhLo);
    cudaGetSymbolAddress((void**)&pB1H, B1Hi); cudaGetSymbolAddress((void**)&pB1L, B1Lo);
    cudaGetSymbolAddress((void**)&pB3H, B3Hi); cudaGetSymbolAddress((void**)&pB3L, B3Lo);
    cudaGetSymbolAddress((void**)&pB4H, B4Hi); cudaGetSymbolAddress((void**)&pB4L, B4Lo);
    cudaGetSymbolAddress((void**)&pb1, gB1);   cudaGetSymbolAddress((void**)&pb3, gB3);

    prep_kernel<<<(NITER * 384 * 128 + 255) / 256, 256>>>(Wm, bm, Wz, Uz, bz, Wr, Ur, br, Wh, Uh, bh);
    embed_kernel<<<ROWS, 128>>>(x, W_emb, b_emb, pos);
    init_s_kernel<<<(ROWS + 255) / 256, 256>>>();
    adj_t<0><<<dim3(NN / 8, BSZ), 128>>>(mask, Aout);

    for (int it = 0; it < NITER; it++) {
        // [m | z_pre | r_pre] = h @ [Wm|Uz|Ur]
        mma_gemm<1><<<dim3(ROWS / 128, 3, 1), 256, SMEM_B>>>(
            phH, phL, HID, 0,
            pB1H + (size_t)it * 384 * 128, pB1L + (size_t)it * 384 * 128, 384, 0,
            HID, pb1 + it * 384, pw0);

        // agg[b] = A[b] @ m[b]
        mma_gemm<0><<<dim3(NN / 128, 1, BSZ), 256, SMEM_B>>>(
            pAH, pAL, NN, (long long)NN * NN,
            pMH, pML, HID, (long long)NN * HID,
            NN, nullptr, pw0);

        // [z | r->rh | p] = agg @ [Wz|Wr|Wh]
        mma_gemm<2><<<dim3(ROWS / 128, 3, 1), 256, SMEM_B>>>(
            paH, paL, HID, 0,
            pB3H + (size_t)it * 384 * 128, pB3L + (size_t)it * 384 * 128, 384, 0,
            HID, pb3 + it * 384, pw0);

        // h = (1-z) h + z tanh(rh@Uh + p)  + fused positional GRU
        mma_gemm<3><<<dim3(ROWS / 128, 1, 1), 256, SMEM_B>>>(
            prH, prL, HID, 0,
            pB4H + (size_t)it * HID * HID, pB4L + (size_t)it * HID * HID, HID, 0,
            HID, nullptr, pw0);

        if (it < NITER - 1)
            adj_t<0><<<dim3(NN / 8, BSZ), 128>>>(mask, Aout);
        else
            adj_t<1><<<dim3(NN / 8, BSZ), 128>>>(mask, Aout);
    }
}

// round 17
// speedup vs baseline: 2.4296x; 1.1575x over previous
#include <cuda_runtime.h>
#include <cuda_bf16.h>
#include <stdint.h>
#include <math.h>

#define BSZ   64
#define NN    512
#define HID   128
#define NITER 3
#define ROWS  (BSZ*NN)

// ---------------- scratch ----------------------------------------------------
__device__ __align__(16) float gH [ROWS*HID];
__device__ __align__(16) float gZ [ROWS*HID];
__device__ __align__(16) float gS [ROWS*3];
__device__ __align__(16) __nv_bfloat16 hHi [ROWS*HID], hLo [ROWS*HID];
__device__ __align__(16) __nv_bfloat16 mHi [ROWS*HID], mLo [ROWS*HID];
__device__ __align__(16) __nv_bfloat16 aggHi[ROWS*HID], aggLo[ROWS*HID];
__device__ __align__(16) __nv_bfloat16 rhHi [ROWS*HID], rhLo [ROWS*HID];
__device__ __align__(16) __nv_bfloat16 BmHi [NITER*128*128], BmLo [NITER*128*128]; // Wm  [k][n]
__device__ __align__(16) __nv_bfloat16 BzrHi[NITER*256*256], BzrLo[NITER*256*256]; // [[Wz|Wr];[Uz|Ur]]
__device__ __align__(16) __nv_bfloat16 BhHi [NITER*256*128], BhLo [NITER*256*128]; // [[Wh];[Uh]]
__device__ __align__(16) float gBm[NITER*128], gBzr[NITER*256], gBh[NITER*128];

struct PosW { const float* p[9]; };

__device__ __forceinline__ float sigm(float x) { return 1.0f / (1.0f + __expf(-x)); }

__device__ __forceinline__ void split2(float v, __nv_bfloat16& hi, __nv_bfloat16& lo)
{
    __nv_bfloat16 h = __float2bfloat16(v);
    hi = h;
    lo = __float2bfloat16(v - __bfloat162float(h));
}

__device__ __forceinline__ uint32_t smem_u32(const void* p)
{
    uint32_t a;
    asm("{ .reg .u64 t; cvta.to.shared.u64 t, %1; cvt.u32.u64 %0, t; }" : "=r"(a) : "l"(p));
    return a;
}

// ---------------- mma.sync building blocks -----------------------------------
__device__ __forceinline__ void mma16816(float* d, const uint32_t* a, const uint32_t* b)
{
    asm volatile(
        "mma.sync.aligned.m16n8k16.row.col.f32.bf16.bf16.f32 "
        "{%0,%1,%2,%3}, {%4,%5,%6,%7}, {%8,%9}, {%0,%1,%2,%3};"
        : "+f"(d[0]), "+f"(d[1]), "+f"(d[2]), "+f"(d[3])
        : "r"(a[0]), "r"(a[1]), "r"(a[2]), "r"(a[3]), "r"(b[0]), "r"(b[1]));
}

__device__ __forceinline__ void ldsm4(uint32_t* r, uint32_t addr)
{
    asm volatile("ldmatrix.sync.aligned.m8n8.x4.shared.b16 {%0,%1,%2,%3}, [%4];"
                 : "=r"(r[0]), "=r"(r[1]), "=r"(r[2]), "=r"(r[3]) : "r"(addr));
}

__device__ __forceinline__ void ldsm4t(uint32_t* r, uint32_t addr)
{
    asm volatile("ldmatrix.sync.aligned.m8n8.x4.trans.shared.b16 {%0,%1,%2,%3}, [%4];"
                 : "=r"(r[0]), "=r"(r[1]), "=r"(r[2]), "=r"(r[3]) : "r"(addr));
}

__device__ __forceinline__ void cp16(uint32_t s, const void* g)
{
    asm volatile("cp.async.cg.shared.global [%0], [%1], 16;" :: "r"(s), "l"(g));
}

#define ASTRIDE 40
#define BSTRIDE 136
#define A_TILE_B (128*ASTRIDE*2)              // 10240
#define B_TILE_B (32*BSTRIDE*2)               // 8704
#define STAGE_STD (2*A_TILE_B + 2*B_TILE_B)   // 37888
#define SMEM_STD  (2*STAGE_STD)               // 75776
// EPI0 (agg, generated A): A single buffer @0 (hi) / +A_TILE_B (lo);
// B double @AGG_B_OFF; mask double @AGG_MK_OFF
#define AGG_B_OFF   (2*A_TILE_B)              // 20480
#define AGG_MK_OFF  (AGG_B_OFF + 4*B_TILE_B)  // 55296
#define SMEM_AGG    (AGG_MK_OFF + 2*16384)    // 88064

__device__ __forceinline__ void load_A_stage(uint32_t dst, int tid,
    const __nv_bfloat16* ah, const __nv_bfloat16* al)
{
#pragma unroll
    for (int i = 0; i < 4; i++) {
        int id = tid + i * 256;
        int t  = id >> 9;
        int r  = (id >> 2) & 127;
        int c  = id & 3;
        const __nv_bfloat16* g = (t ? al : ah) + (long long)r * HID + c * 8;
        cp16(dst + t * A_TILE_B + r * (ASTRIDE * 2) + c * 16, g);
    }
}

__device__ __forceinline__ void load_B_stage(uint32_t dst, int tid,
    const __nv_bfloat16* bh_, const __nv_bfloat16* bl_, int ldb, int k0)
{
#pragma unroll
    for (int i = 0; i < 4; i++) {
        int id = tid + i * 256;
        int t  = id >> 9;
        int r  = (id >> 4) & 31;
        int c  = id & 15;
        const __nv_bfloat16* g = (t ? bl_ : bh_) + (long long)(k0 + r) * ldb + c * 8;
        cp16(dst + t * B_TILE_B + r * (BSTRIDE * 2) + c * 16, g);
    }
}

__device__ __forceinline__ void load_M_stage(uint32_t dst, int tid,
    const float* mb, int j0)
{
#pragma unroll
    for (int i = 0; i < 4; i++) {
        int id = tid + i * 256;     // 1024 chunks: 128 rows x 8 x 16B
        int r  = id >> 3;
        int c  = id & 7;
        cp16(dst + r * 128 + c * 16, mb + (long long)r * NN + j0 + c * 4);
    }
}

// generate A tile (128 x 32) = exp(-100*d2)*mask, split bf16, ldmatrix layout
__device__ __forceinline__ void gen_A(char* smem, int kt, int wid, int lane,
                                      int bz, int bm)
{
    const float* ms = (const float*)(smem + AGG_MK_OFF + (kt & 1) * 16384);
    __nv_bfloat16* aH = (__nv_bfloat16*)(smem);
    __nv_bfloat16* aL = (__nv_bfloat16*)(smem + A_TILE_B);
    long long sjb = ((long long)bz * NN + kt * 32 + lane) * 3;
    float sjx = gS[sjb], sjy = gS[sjb + 1], sjz = gS[sjb + 2];
    long long sib0 = ((long long)bz * NN + bm * 128) * 3;
#pragma unroll
    for (int ii = 0; ii < 16; ii++) {
        int i = wid * 16 + ii;
        float six = gS[sib0 + i * 3], siy = gS[sib0 + i * 3 + 1], siz = gS[sib0 + i * 3 + 2];
        float dx = six - sjx, dy = siy - sjy, dz = siz - sjz;
        float a = __expf(-100.0f * (dx * dx + dy * dy + dz * dz)) * ms[i * 32 + lane];
        __nv_bfloat16 h, l;
        split2(a, h, l);
        aH[i * ASTRIDE + lane] = h;
        aL[i * ASTRIDE + lane] = l;
    }
}

// ---------------- split-bf16 tensor-core GEMM (mma.sync) ---------------------
// EPI 0: agg = A_gen @ m            (grid (4,1,64), K=512, A generated)
// EPI 1: m   = relu(h@Wm + bm)      (grid (256,1,1), K=128)
// EPI 2: [z|r] = sigm([agg,h]@Bzr+b) yy=0 -> gZ ; yy=1 -> rh splits (grid (256,2,1), K=256)
// EPI 3: h = (1-z)h + z tanh([agg,rh]@Bh + bh) + fused posgru (grid (256,1,1), K=256)
template <int EPI>
__global__ void __launch_bounds__(256, 2)
mma_gemm(const __nv_bfloat16* __restrict__ A1h, const __nv_bfloat16* __restrict__ A1l,
         const __nv_bfloat16* __restrict__ A2h, const __nv_bfloat16* __restrict__ A2l,
         const __nv_bfloat16* __restrict__ Bh,  const __nv_bfloat16* __restrict__ Bl,
         int ldb, long long sB, const float* __restrict__ mask,
         int K, const float* __restrict__ bias, PosW pw)
{
    extern __shared__ char smem[];
    const uint32_t sb = smem_u32(smem);
    const int tid = threadIdx.x;
    const int wid = tid >> 5, lane = tid & 31;
    const int wm = wid >> 1, wn = wid & 1;
    const int bm = blockIdx.x, yy = blockIdx.y, bz = blockIdx.z;

    const __nv_bfloat16* B0h = Bh + bz * sB + yy * 128;
    const __nv_bfloat16* B0l = Bl + bz * sB + yy * 128;
    const long long arow0 = (long long)bm * 128 * HID;
    const __nv_bfloat16* A1hb = A1h + arow0;
    const __nv_bfloat16* A1lb = A1l + arow0;
    const __nv_bfloat16* A2hb = A2h + arow0;
    const __nv_bfloat16* A2lb = A2l + arow0;
    const float* mb = (EPI == 0) ? mask + ((long long)bz * NN + bm * 128) * NN : nullptr;

    float acc[2][8][4];
#pragma unroll
    for (int i = 0; i < 2; i++)
#pragma unroll
        for (int j = 0; j < 8; j++)
#pragma unroll
            for (int e = 0; e < 4; e++) acc[i][j][e] = 0.0f;

    const uint32_t aoff = (uint32_t)((wm * 32 + (lane & 15)) * (ASTRIDE * 2) + (lane >> 4) * 16);
    const int q = lane >> 3;
    const uint32_t boff = (uint32_t)(((q & 1) * 8 + (lane & 7)) * (BSTRIDE * 2)
                        + (wn * 64 + (q >> 1) * 8) * 2);

    const int nstage = K >> 5;

    // prologue: stage 0 loads
    if (EPI == 0) {
        load_B_stage(sb + AGG_B_OFF, tid, B0h, B0l, ldb, 0);
        load_M_stage(sb + AGG_MK_OFF, tid, mb, 0);
    } else {
        load_A_stage(sb, tid, A1hb, A1lb);
        load_B_stage(sb + 2 * A_TILE_B, tid, B0h, B0l, ldb, 0);
    }
    asm volatile("cp.async.commit_group;" ::: "memory");

    for (int kt = 0; kt < nstage; kt++) {
        asm volatile("cp.async.wait_group 0;" ::: "memory");
        __syncthreads();

        if (kt + 1 < nstage) {
            const int k0n = (kt + 1) << 5;
            const int buf = (kt + 1) & 1;
            if (EPI == 0) {
                load_B_stage(sb + AGG_B_OFF + buf * (2 * B_TILE_B), tid, B0h, B0l, ldb, k0n);
                load_M_stage(sb + AGG_MK_OFF + buf * 16384, tid, mb, k0n);
            } else {
                const __nv_bfloat16 *ah, *al;
                if (k0n < 128) { ah = A1hb + k0n; al = A1lb + k0n; }
                else           { ah = A2hb + (k0n - 128); al = A2lb + (k0n - 128); }
                load_A_stage(sb + buf * STAGE_STD, tid, ah, al);
                load_B_stage(sb + buf * STAGE_STD + 2 * A_TILE_B, tid, B0h, B0l, ldb, k0n);
            }
            asm volatile("cp.async.commit_group;" ::: "memory");
        }

        if (EPI == 0) {
            gen_A(smem, kt, wid, lane, bz, bm);
            __syncthreads();
        }

        const uint32_t Ab = (EPI == 0) ? sb : sb + (kt & 1) * STAGE_STD;
        const uint32_t Bb = (EPI == 0) ? sb + AGG_B_OFF + (kt & 1) * (2 * B_TILE_B)
                                       : sb + (kt & 1) * STAGE_STD + 2 * A_TILE_B;
#pragma unroll
        for (int j = 0; j < 2; j++) {
            uint32_t ah[2][4], al[2][4];
#pragma unroll
            for (int mt = 0; mt < 2; mt++) {
                uint32_t a0 = Ab + aoff + mt * 16 * (ASTRIDE * 2) + j * 32;
                ldsm4(ah[mt], a0);
                ldsm4(al[mt], a0 + A_TILE_B);
            }
#pragma unroll
            for (int np = 0; np < 4; np++) {
                uint32_t bh2[4], bl2[4];
                uint32_t b0 = Bb + boff + j * 16 * (BSTRIDE * 2) + np * 32;
                ldsm4t(bh2, b0);
                ldsm4t(bl2, b0 + B_TILE_B);
#pragma unroll
                for (int mt = 0; mt < 2; mt++) {
                    mma16816(acc[mt][2 * np],     ah[mt], bh2);
                    mma16816(acc[mt][2 * np],     ah[mt], bl2);
                    mma16816(acc[mt][2 * np],     al[mt], bh2);
                    mma16816(acc[mt][2 * np + 1], ah[mt], bh2 + 2);
                    mma16816(acc[mt][2 * np + 1], ah[mt], bl2 + 2);
                    mma16816(acc[mt][2 * np + 1], al[mt], bh2 + 2);
                }
            }
        }
    }

    float* hs = (float*)smem;          // EPI3: 64 KB staging for fused posgru
    if (EPI == 3) __syncthreads();

    const int lrow = lane >> 2;
    const int lcol = (lane & 3) * 2;
#pragma unroll
    for (int mt = 0; mt < 2; mt++)
#pragma unroll
    for (int nt = 0; nt < 8; nt++)
#pragma unroll
    for (int half = 0; half < 2; half++) {
        const int rloc = wm * 32 + mt * 16 + lrow + half * 8;
        const int col = wn * 64 + nt * 8 + lcol;
        float v0 = acc[mt][nt][half * 2 + 0];
        float v1 = acc[mt][nt][half * 2 + 1];

        if (EPI == 0) {
            long long base = ((long long)bz * NN + bm * 128 + rloc) * HID + col;
            __nv_bfloat162 hv, lv;
            split2(v0, hv.x, lv.x); split2(v1, hv.y, lv.y);
            *(__nv_bfloat162*)(aggHi + base) = hv;
            *(__nv_bfloat162*)(aggLo + base) = lv;
        } else if (EPI == 1) {
            int base = (bm * 128 + rloc) * HID + col;
            float m0 = fmaxf(v0 + bias[col],     0.0f);
            float m1 = fmaxf(v1 + bias[col + 1], 0.0f);
            __nv_bfloat162 hv, lv;
            split2(m0, hv.x, lv.x); split2(m1, hv.y, lv.y);
            *(__nv_bfloat162*)(mHi + base) = hv;
            *(__nv_bfloat162*)(mLo + base) = lv;
        } else if (EPI == 2) {
            int base = (bm * 128 + rloc) * HID + col;
            float g0 = sigm(v0 + bias[yy * 128 + col]);
            float g1 = sigm(v1 + bias[yy * 128 + col + 1]);
            if (yy == 0) {
                float2 o; o.x = g0; o.y = g1;
                *(float2*)(gZ + base) = o;
            } else {
                float2 h2 = *(const float2*)(gH + base);
                __nv_bfloat162 hv, lv;
                split2(g0 * h2.x, hv.x, lv.x);
                split2(g1 * h2.y, hv.y, lv.y);
                *(__nv_bfloat162*)(rhHi + base) = hv;
                *(__nv_bfloat162*)(rhLo + base) = lv;
            }
        } else { // EPI == 3
            int base = (bm * 128 + rloc) * HID + col;
            float2 z  = *(const float2*)(gZ + base);
            float2 h2 = *(const float2*)(gH + base);
            float hn0 = fmaf(z.x, tanhf(v0 + bias[col])     - h2.x, h2.x);
            float hn1 = fmaf(z.y, tanhf(v1 + bias[col + 1]) - h2.y, h2.y);
            float2 o; o.x = hn0; o.y = hn1;
            *(float2*)(gH + base) = o;
            hs[rloc * HID + col]     = hn0;
            hs[rloc * HID + col + 1] = hn1;
            __nv_bfloat162 hv, lv;
            split2(hn0, hv.x, lv.x); split2(hn1, hv.y, lv.y);
            *(__nv_bfloat162*)(hHi + base) = hv;
            *(__nv_bfloat162*)(hLo + base) = lv;
        }
    }

    if (EPI == 3) {
        __syncthreads();
        const float* Wpz = pw.p[0]; const float* Upz = pw.p[1]; const float* bpz = pw.p[2];
        const float* Wpr = pw.p[3]; const float* Upr = pw.p[4]; const float* bpr = pw.p[5];
        const float* Wph = pw.p[6]; const float* Uph = pw.p[7]; const float* bph = pw.p[8];
#pragma unroll 1
        for (int t = 0; t < 16; t++) {
            const int nloc = wid * 16 + t;
            const int node = bm * 128 + nloc;
            const float* hrow = hs + nloc * HID;
            float pz[3] = {0,0,0}, pr[3] = {0,0,0}, ph[3] = {0,0,0};
#pragma unroll
            for (int qq = 0; qq < 4; qq++) {
                int e = lane + qq * 32;
                float hv = hrow[e];
#pragma unroll
                for (int c = 0; c < 3; c++) {
                    pz[c] = fmaf(hv, Wpz[e * 3 + c], pz[c]);
                    pr[c] = fmaf(hv, Wpr[e * 3 + c], pr[c]);
                    ph[c] = fmaf(hv, Wph[e * 3 + c], ph[c]);
                }
            }
#pragma unroll
            for (int off = 16; off; off >>= 1) {
#pragma unroll
                for (int c = 0; c < 3; c++) {
                    pz[c] += __shfl_xor_sync(0xffffffffu, pz[c], off);
                    pr[c] += __shfl_xor_sync(0xffffffffu, pr[c], off);
                    ph[c] += __shfl_xor_sync(0xffffffffu, ph[c], off);
                }
            }
            if (lane == 0) {
                float s0 = gS[node*3+0], s1 = gS[node*3+1], s2 = gS[node*3+2];
                float zs[3], rs[3], ss[3];
#pragma unroll
                for (int c = 0; c < 3; c++)
                    zs[c] = sigm(pz[c] + s0*Upz[c] + s1*Upz[3+c] + s2*Upz[6+c] + bpz[c]);
#pragma unroll
                for (int c = 0; c < 3; c++)
                    rs[c] = sigm(pr[c] + s0*Upr[c] + s1*Upr[3+c] + s2*Upr[6+c] + bpr[c]);
                float t0 = rs[0]*s0, t1 = rs[1]*s1, t2 = rs[2]*s2;
#pragma unroll
                for (int c = 0; c < 3; c++)
                    ss[c] = tanhf(ph[c] + t0*Uph[c] + t1*Uph[3+c] + t2*Uph[6+c] + bph[c]);
                gS[node*3+0] = (1.0f - zs[0])*s0 + zs[0]*ss[0];
                gS[node*3+1] = (1.0f - zs[1])*s1 + zs[1]*ss[1];
                gS[node*3+2] = (1.0f - zs[2])*s2 + zs[2]*ss[2];
            }
        }
    }
}

// ---------------- weight panel prep -------------------------------------------
__global__ void prep_kernel(const float* __restrict__ Wm, const float* __restrict__ bm_,
                            const float* __restrict__ Wz, const float* __restrict__ Uz, const float* __restrict__ bz_,
                            const float* __restrict__ Wr, const float* __restrict__ Ur, const float* __restrict__ br_,
                            const float* __restrict__ Wh, const float* __restrict__ Uh, const float* __restrict__ bh_)
{
    int idx = blockIdx.x * 256 + threadIdx.x;
    if (idx >= NITER * 256 * 256) return;
    int it  = idx / 65536;
    int rem = idx & 65535;
    int kk = rem >> 8;
    int nn = rem & 255;
    float w;
    if (kk < 128) w = (nn < 128) ? Wz[it*16384 + kk*128 + nn] : Wr[it*16384 + kk*128 + nn - 128];
    else          w = (nn < 128) ? Uz[it*16384 + (kk-128)*128 + nn] : Ur[it*16384 + (kk-128)*128 + nn - 128];
    split2(w, BzrHi[idx], BzrLo[idx]);
    if (nn < 128) {
        float w2 = (kk < 128) ? Wh[it*16384 + kk*128 + nn] : Uh[it*16384 + (kk-128)*128 + nn];
        int o = it*32768 + kk*128 + nn;
        split2(w2, BhHi[o], BhLo[o]);
        if (kk < 128) {
            int o2 = it*16384 + kk*128 + nn;
            split2(Wm[o2], BmHi[o2], BmLo[o2]);
        }
    }
    if (kk == 0) {
        gBzr[it*256 + nn] = (nn < 128) ? bz_[it*128 + nn] : br_[it*128 + nn - 128];
        if (nn < 128) {
            gBm[it*128 + nn] = bm_[it*128 + nn];
            gBh[it*128 + nn] = bh_[it*128 + nn];
        }
    }
}

// ---------------- embedding ---------------------------------------------------
__global__ void embed_kernel(const float* __restrict__ x, const float* __restrict__ W,
                             const float* __restrict__ b, const float* __restrict__ pos)
{
    __shared__ float xs[64];
    int row = blockIdx.x;
    int c = threadIdx.x;
    if (c < 64) xs[c] = x[(size_t)row * 64 + c];
    __syncthreads();
    float acc = b[c];
#pragma unroll 16
    for (int f = 0; f < 64; f++) acc = fmaf(xs[f], W[f * HID + c], acc);
    int n = row & (NN - 1);
    float h = fmaxf(acc, 0.0f) + pos[n * HID + c];
    int o = row * HID + c;
    gH[o] = h;
    split2(h, hHi[o], hLo[o]);
}

__global__ void init_s_kernel()
{
    int idx = blockIdx.x * blockDim.x + threadIdx.x;
    if (idx < ROWS) {
        int j = idx & (NN - 1);
        gS[idx * 3 + 0] = (j - 255.5f) * (1.0f / NN);
        gS[idx * 3 + 1] = 0.0f;
        gS[idx * 3 + 2] = 0.0f;
    }
}

// ---------------- final adjacency -> d_out (fp32) ------------------------------
__global__ void adj_out(const float* __restrict__ mask, float* __restrict__ Aout)
{
    int b  = blockIdx.y;
    int i0 = blockIdx.x * 8;
    __shared__ float sx[NN], sy[NN], sz[NN];
    const float* s = gS + (size_t)b * NN * 3;
    for (int j = threadIdx.x; j < NN; j += 128) {
        sx[j] = s[j * 3 + 0]; sy[j] = s[j * 3 + 1]; sz[j] = s[j * 3 + 2];
    }
    __syncthreads();
    int j0 = threadIdx.x * 4;
#pragma unroll
    for (int rr = 0; rr < 8; rr++) {
        int i = i0 + rr;
        float xi = sx[i], yi = sy[i], zi = sz[i];
        size_t base = ((size_t)b * NN + i) * NN + j0;
        float4 mv = *(const float4*)(mask + base);
        float4 ov;
#pragma unroll
        for (int t = 0; t < 4; t++) {
            int j = j0 + t;
            float dx = xi - sx[j], dy = yi - sy[j], dz = zi - sz[j];
            (&ov.x)[t] = __expf(-100.0f * (dx * dx + dy * dy + dz * dz)) * ((&mv.x)[t]);
        }
        *(float4*)(Aout + base) = ov;
    }
}

// ---------------- launch ---------------------------------------------------------
extern "C" void kernel_launch(void* const* d_in, const int* in_sizes, int n_in,
                              void* d_out, int out_size)
{
    const float* x     = (const float*)d_in[0];
    const float* mask  = (const float*)d_in[1];
    const float* W_emb = (const float*)d_in[2];
    const float* b_emb = (const float*)d_in[3];
    const float* pos   = (const float*)d_in[4];
    const float* Wm    = (const float*)d_in[5];
    const float* bm    = (const float*)d_in[6];
    const float* Wz    = (const float*)d_in[7];
    const float* Uz    = (const float*)d_in[8];
    const float* bz    = (const float*)d_in[9];
    const float* Wr    = (const float*)d_in[10];
    const float* Ur    = (const float*)d_in[11];
    const float* br    = (const float*)d_in[12];
    const float* Wh    = (const float*)d_in[13];
    const float* Uh    = (const float*)d_in[14];
    const float* bh    = (const float*)d_in[15];
    PosW pw;
    for (int i = 0; i < 9; i++) pw.p[i] = (const float*)d_in[16 + i];
    float* Aout = (float*)d_out;

    cudaFuncSetAttribute(mma_gemm<0>, cudaFuncAttributeMaxDynamicSharedMemorySize, SMEM_AGG);
    cudaFuncSetAttribute(mma_gemm<1>, cudaFuncAttributeMaxDynamicSharedMemorySize, SMEM_STD);
    cudaFuncSetAttribute(mma_gemm<2>, cudaFuncAttributeMaxDynamicSharedMemorySize, SMEM_STD);
    cudaFuncSetAttribute(mma_gemm<3>, cudaFuncAttributeMaxDynamicSharedMemorySize, SMEM_STD);

    __nv_bfloat16 *pMH, *pML, *phH, *phL, *paH, *paL, *prH, *prL;
    __nv_bfloat16 *pBmH, *pBmL, *pBzH, *pBzL, *pBhH, *pBhL;
    float *pbm, *pbzr, *pbh;
    cudaGetSymbolAddress((void**)&pMH, mHi);   cudaGetSymbolAddress((void**)&pML, mLo);
    cudaGetSymbolAddress((void**)&phH, hHi);   cudaGetSymbolAddress((void**)&phL, hLo);
    cudaGetSymbolAddress((void**)&paH, aggHi); cudaGetSymbolAddress((void**)&paL, aggLo);
    cudaGetSymbolAddress((void**)&prH, rhHi);  cudaGetSymbolAddress((void**)&prL, rhLo);
    cudaGetSymbolAddress((void**)&pBmH, BmHi); cudaGetSymbolAddress((void**)&pBmL, BmLo);
    cudaGetSymbolAddress((void**)&pBzH, BzrHi);cudaGetSymbolAddress((void**)&pBzL, BzrLo);
    cudaGetSymbolAddress((void**)&pBhH, BhHi); cudaGetSymbolAddress((void**)&pBhL, BhLo);
    cudaGetSymbolAddress((void**)&pbm, gBm);   cudaGetSymbolAddress((void**)&pbzr, gBzr);
    cudaGetSymbolAddress((void**)&pbh, gBh);

    prep_kernel<<<(NITER * 256 * 256 + 255) / 256, 256>>>(Wm, bm, Wz, Uz, bz, Wr, Ur, br, Wh, Uh, bh);
    embed_kernel<<<ROWS, 128>>>(x, W_emb, b_emb, pos);
    init_s_kernel<<<(ROWS + 255) / 256, 256>>>();

    for (int it = 0; it < NITER; it++) {
        // m = relu(h @ Wm + bm)
        mma_gemm<1><<<dim3(ROWS / 128, 1, 1), 256, SMEM_STD>>>(
            phH, phL, phH, phL,
            pBmH + (size_t)it * 16384, pBmL + (size_t)it * 16384, 128, 0,
            nullptr, 128, pbm + it * 128, pw);

        // agg[b] = A_gen(s, mask) @ m[b]
        mma_gemm<0><<<dim3(NN / 128, 1, BSZ), 256, SMEM_AGG>>>(
            pMH, pML, pMH, pML,
            pMH, pML, 128, (long long)NN * HID,
            mask, NN, nullptr, pw);

        // [z | r] = sigm([agg, h] @ Bzr + [bz|br]); yy=1 also forms rh splits
        mma_gemm<2><<<dim3(ROWS / 128, 2, 1), 256, SMEM_STD>>>(
            paH, paL, phH, phL,
            pBzH + (size_t)it * 65536, pBzL + (size_t)it * 65536, 256, 0,
            nullptr, 256, pbzr + it * 256, pw);

        // h = (1-z) h + z tanh([agg, rh] @ Bh + bh)  + fused posgru
        mma_gemm<3><<<dim3(ROWS / 128, 1, 1), 256, SMEM_STD>>>(
            paH, paL, prH, prL,
            pBhH + (size_t)it * 32768, pBhL + (size_t)it * 32768, 128, 0,
            nullptr, 256, pbh + it * 128, pw);
    }

    adj_out<<<dim3(NN / 8, BSZ), 128>>>(mask, Aout);
}